// round 2
// baseline (speedup 1.0000x reference)
#include <cuda_runtime.h>
#include <math.h>

#define BATCH 512
#define TT    256
#define DD    32
#define HH    256
#define M_TOTAL (BATCH*TT)
#define PSTR  (BATCH*4*TT*64)   // 33554432, per-part stride in QKVg

// ---------------- static device scratch (no allocations) ----------------
__device__ float P0w[289*1024];
__device__ float P1w[512*1024];
__device__ float bs0w[1024];
__device__ float bs1w[1024];
__device__ float PFw[256*256];      // PF[k][r] = W1[r][k] + W1[r][256+k]
__device__ float W1aTw[256*256];    // [k][r] = W1[r][k]
__device__ float WcombTw[256*256];  // [m][r] = sum_j W1[r][256+j] * Wop[j][m]
__device__ float b1fw[256];
__device__ float Lg[M_TOTAL*HH];
__device__ float CTXg[M_TOTAL*HH];
__device__ float QKVg[3*PSTR];

__device__ __forceinline__ float sigf(float x) { return 1.f / (1.f + __expf(-x)); }
__device__ __forceinline__ float tanh_f(float x) {
    x = fmaxf(fminf(x, 30.f), -30.f);
    float z = __expf(-2.f * x);
    return (1.f - z) / (1.f + z);
}

// ---------------- prep ----------------
__global__ void prep_pack(const float* __restrict__ Wih0, const float* __restrict__ Whh0,
                          const float* __restrict__ bih0, const float* __restrict__ bhh0,
                          const float* __restrict__ Wih1, const float* __restrict__ Whh1,
                          const float* __restrict__ bih1, const float* __restrict__ bhh1,
                          const float* __restrict__ W1) {
    int i = blockIdx.x * 256 + threadIdx.x;
    const int S0 = 289*1024;            // 295936
    const int S1 = S0 + 512*1024;       // 820224
    const int S2 = S1 + 65536;          // 885760
    const int S3 = S2 + 65536;          // 951296
    const int S4 = S3 + 1024;           // 952320
    const int S5 = S4 + 1024;           // 953344
    if (i < S0) {
        int k = i >> 10, j = i & 1023;
        P0w[i] = (k < 33) ? Wih0[j*33 + k] : Whh0[j*256 + (k-33)];
    } else if (i < S1) {
        int e = i - S0; int k = e >> 10, j = e & 1023;
        P1w[e] = (k < 256) ? Wih1[j*256 + k] : Whh1[j*256 + (k-256)];
    } else if (i < S2) {
        int e = i - S1; int k = e >> 8, r = e & 255;
        PFw[e] = W1[r*512 + k] + W1[r*512 + 256 + k];
    } else if (i < S3) {
        int e = i - S2; int k = e >> 8, r = e & 255;
        W1aTw[e] = W1[r*512 + k];
    } else if (i < S4) {
        int e = i - S3; bs0w[e] = bih0[e] + bhh0[e];
    } else if (i < S5) {
        int e = i - S4; bs1w[e] = bih1[e] + bhh1[e];
    }
}

__global__ void prep_wcomb(const float* __restrict__ W1, const float* __restrict__ Wop) {
    int r = blockIdx.x, m = threadIdx.x;
    float s = 0.f;
    for (int k = 0; k < 256; k++) s += W1[r*512 + 256 + k] * Wop[k*256 + m];
    WcombTw[m*256 + r] = s;
}

__global__ void prep_b1f(const float* __restrict__ b1, const float* __restrict__ bop,
                         const float* __restrict__ W1) {
    int r = threadIdx.x;
    float s = b1[r];
    for (int k = 0; k < 256; k++) s += bop[k] * W1[r*512 + 256 + k];
    b1fw[r] = s;
}

// ---------------- recurrent scan: 128 blocks x 4 batch rows ----------------
__global__ void __launch_bounds__(256) scan_kernel(const float* __restrict__ F,
                                                   const float* __restrict__ b1,
                                                   const float* __restrict__ W2,
                                                   const float* __restrict__ b2p) {
    __shared__ float h1s[4][256];
    __shared__ float h2s[4][256];
    __shared__ float xs[4][32];
    __shared__ float pds[4];
    __shared__ float red[8][4];

    const int n = threadIdx.x;
    const int b0 = blockIdx.x * 4;
    const int lane = n & 31, wid = n >> 5;

    float c1[4] = {0.f,0.f,0.f,0.f};
    float c2[4] = {0.f,0.f,0.f,0.f};
#pragma unroll
    for (int r = 0; r < 4; r++) { h1s[r][n] = 0.f; h2s[r][n] = 0.f; }
    if (n < 4) pds[n] = 0.f;

    float bi0[4], bi1[4];
#pragma unroll
    for (int g = 0; g < 4; g++) { bi0[g] = bs0w[g*256 + n]; bi1[g] = bs1w[g*256 + n]; }
    const float b1n = b1[n];
    const float w2n = W2[n];
    const float b2v = b2p[0];

    __syncthreads();

    for (int t = 0; t < TT; t++) {
        if (n < 128) {
            int r = n >> 5, k = n & 31;
            xs[r][k] = F[(size_t)(b0 + r)*(TT*DD) + t*DD + k];
        }
        __syncthreads();

        float a0[4], a1[4], a2[4], a3[4];
#pragma unroll
        for (int r = 0; r < 4; r++) { a0[r]=bi0[0]; a1[r]=bi0[1]; a2[r]=bi0[2]; a3[r]=bi0[3]; }
        const float* p0 = P0w + n;
#pragma unroll 4
        for (int k = 0; k < 32; k++) {
            float w0=p0[k*1024], w1=p0[k*1024+256], w2v=p0[k*1024+512], w3=p0[k*1024+768];
#pragma unroll
            for (int r = 0; r < 4; r++) {
                float v = xs[r][k];
                a0[r]+=w0*v; a1[r]+=w1*v; a2[r]+=w2v*v; a3[r]+=w3*v;
            }
        }
        {
            float w0=p0[32*1024], w1=p0[32*1024+256], w2v=p0[32*1024+512], w3=p0[32*1024+768];
#pragma unroll
            for (int r = 0; r < 4; r++) {
                float v = pds[r];
                a0[r]+=w0*v; a1[r]+=w1*v; a2[r]+=w2v*v; a3[r]+=w3*v;
            }
        }
        const float* ph = P0w + 33*1024 + n;
#pragma unroll 4
        for (int k = 0; k < 256; k++) {
            float w0=ph[k*1024], w1=ph[k*1024+256], w2v=ph[k*1024+512], w3=ph[k*1024+768];
#pragma unroll
            for (int r = 0; r < 4; r++) {
                float v = h1s[r][k];
                a0[r]+=w0*v; a1[r]+=w1*v; a2[r]+=w2v*v; a3[r]+=w3*v;
            }
        }
        float h1n[4];
#pragma unroll
        for (int r = 0; r < 4; r++) {
            float iv=sigf(a0[r]), fv=sigf(a1[r]), gv=tanh_f(a2[r]), ov=sigf(a3[r]);
            c1[r] = fv*c1[r] + iv*gv;
            h1n[r] = ov * tanh_f(c1[r]);
        }
        __syncthreads();
#pragma unroll
        for (int r = 0; r < 4; r++) h1s[r][n] = h1n[r];
        __syncthreads();

#pragma unroll
        for (int r = 0; r < 4; r++) { a0[r]=bi1[0]; a1[r]=bi1[1]; a2[r]=bi1[2]; a3[r]=bi1[3]; }
        const float* q0 = P1w + n;
#pragma unroll 4
        for (int k = 0; k < 256; k++) {
            float w0=q0[k*1024], w1=q0[k*1024+256], w2v=q0[k*1024+512], w3=q0[k*1024+768];
#pragma unroll
            for (int r = 0; r < 4; r++) {
                float v = h1s[r][k];
                a0[r]+=w0*v; a1[r]+=w1*v; a2[r]+=w2v*v; a3[r]+=w3*v;
            }
        }
        const float* q1 = P1w + 256*1024 + n;
#pragma unroll 4
        for (int k = 0; k < 256; k++) {
            float w0=q1[k*1024], w1=q1[k*1024+256], w2v=q1[k*1024+512], w3=q1[k*1024+768];
#pragma unroll
            for (int r = 0; r < 4; r++) {
                float v = h2s[r][k];
                a0[r]+=w0*v; a1[r]+=w1*v; a2[r]+=w2v*v; a3[r]+=w3*v;
            }
        }
        float h2n[4];
#pragma unroll
        for (int r = 0; r < 4; r++) {
            float iv=sigf(a0[r]), fv=sigf(a1[r]), gv=tanh_f(a2[r]), ov=sigf(a3[r]);
            c2[r] = fv*c2[r] + iv*gv;
            h2n[r] = ov * tanh_f(c2[r]);
        }
        __syncthreads();
#pragma unroll
        for (int r = 0; r < 4; r++) {
            h2s[r][n] = h2n[r];
            Lg[(size_t)(b0 + r)*(TT*HH) + t*HH + n] = h2n[r];
        }
        __syncthreads();

        // fc -> pd (thread n = hidden unit)
        float v[4] = {b1n, b1n, b1n, b1n};
#pragma unroll 4
        for (int k = 0; k < 256; k++) {
            float w = PFw[k*256 + n];
#pragma unroll
            for (int r = 0; r < 4; r++) v[r] += h2s[r][k] * w;
        }
        float pr[4];
#pragma unroll
        for (int r = 0; r < 4; r++) pr[r] = w2n * fmaxf(v[r], 0.f);
#pragma unroll
        for (int off = 16; off > 0; off >>= 1)
#pragma unroll
            for (int r = 0; r < 4; r++) pr[r] += __shfl_down_sync(0xffffffffu, pr[r], off);
        if (lane == 0)
#pragma unroll
            for (int r = 0; r < 4; r++) red[wid][r] = pr[r];
        __syncthreads();
        if (n < 4) {
            float s = b2v;
#pragma unroll
            for (int w = 0; w < 8; w++) s += red[w][n];
            pds[n] = s;
        }
        __syncthreads();
    }
}

// ---------------- qkv GEMM: C[m][n] = Lg[m][:] . Winp[n][:] + binp[n] ----------------
__global__ void __launch_bounds__(256) qkv_kernel(const float* __restrict__ Winp,
                                                  const float* __restrict__ binp) {
    __shared__ float As[16][128];
    __shared__ float Bs[16][128];
    const int m0 = blockIdx.x * 128;
    const int n0 = blockIdx.y * 128;
    const int tid = threadIdx.x;
    const int tx = tid & 15, ty = tid >> 4;
    float acc[8][8];
#pragma unroll
    for (int i = 0; i < 8; i++)
#pragma unroll
        for (int j = 0; j < 8; j++) acc[i][j] = 0.f;

    for (int k0 = 0; k0 < 256; k0 += 16) {
#pragma unroll
        for (int i = 0; i < 2; i++) {
            int idx = tid + i*256;          // 0..511
            int m = idx >> 2, q = idx & 3;
            float4 a = *(const float4*)&Lg[(size_t)(m0+m)*256 + k0 + q*4];
            As[q*4+0][m]=a.x; As[q*4+1][m]=a.y; As[q*4+2][m]=a.z; As[q*4+3][m]=a.w;
            float4 w = *(const float4*)&Winp[(size_t)(n0+m)*256 + k0 + q*4];
            Bs[q*4+0][m]=w.x; Bs[q*4+1][m]=w.y; Bs[q*4+2][m]=w.z; Bs[q*4+3][m]=w.w;
        }
        __syncthreads();
#pragma unroll
        for (int k = 0; k < 16; k++) {
            float a[8], b[8];
            *(float4*)&a[0] = *(float4*)&As[k][ty*8];
            *(float4*)&a[4] = *(float4*)&As[k][ty*8+4];
            *(float4*)&b[0] = *(float4*)&Bs[k][tx*8];
            *(float4*)&b[4] = *(float4*)&Bs[k][tx*8+4];
#pragma unroll
            for (int i = 0; i < 8; i++)
#pragma unroll
                for (int j = 0; j < 8; j++) acc[i][j] += a[i]*b[j];
        }
        __syncthreads();
    }

    int n_base = n0 + tx*8;
    float bi[8];
#pragma unroll
    for (int j = 0; j < 8; j++) bi[j] = binp[n_base + j];
    int part = n_base >> 8;
    int rem  = n_base & 255;
    int head = rem >> 6;
    int d0   = rem & 63;
#pragma unroll
    for (int i = 0; i < 8; i++) {
        int m = m0 + ty*8 + i;
        int bb = m >> 8, tt = m & 255;
        float* dst = QKVg + ((size_t)((part*BATCH + bb)*4 + head)*TT + tt)*64 + d0;
        float4 o0 = make_float4(acc[i][0]+bi[0], acc[i][1]+bi[1], acc[i][2]+bi[2], acc[i][3]+bi[3]);
        float4 o1 = make_float4(acc[i][4]+bi[4], acc[i][5]+bi[5], acc[i][6]+bi[6], acc[i][7]+bi[7]);
        *(float4*)&dst[0] = o0;
        *(float4*)&dst[4] = o1;
    }
}

// ---------------- attention: block = (b, head), thread = query row ----------------
__global__ void __launch_bounds__(256) attn_kernel() {
    __shared__ float4 Ks[64][16];
    __shared__ float4 Vs[64][16];
    const int b = blockIdx.x, h = blockIdx.y;
    const int t = threadIdx.x;
    const float* Qb = QKVg + ((size_t)(b*4 + h))*TT*64;
    const float* Kb = Qb + PSTR;
    const float* Vb = Kb + PSTR;

    float4 q[16], acc[16];
#pragma unroll
    for (int i = 0; i < 16; i++) {
        q[i] = *(const float4*)&Qb[t*64 + i*4];
        acc[i] = make_float4(0.f, 0.f, 0.f, 0.f);
    }
    float sum = 0.f;

    for (int kc = 0; kc < 4; kc++) {
#pragma unroll
        for (int j = 0; j < 4; j++) {
            int f = t + j*256;                 // 0..1023
            int row = f >> 4, c = f & 15;
            Ks[row][c] = *(const float4*)&Kb[(size_t)(kc*64 + row)*64 + c*4];
            Vs[row][c] = *(const float4*)&Vb[(size_t)(kc*64 + row)*64 + c*4];
        }
        __syncthreads();
#pragma unroll 2
        for (int k = 0; k < 64; k++) {
            float s = 0.f;
#pragma unroll
            for (int i = 0; i < 16; i++) {
                float4 kv = Ks[k][i];
                s += q[i].x*kv.x + q[i].y*kv.y + q[i].z*kv.z + q[i].w*kv.w;
            }
            float p = __expf(s * 0.125f);
            sum += p;
#pragma unroll
            for (int i = 0; i < 16; i++) {
                float4 vv = Vs[k][i];
                acc[i].x += p*vv.x; acc[i].y += p*vv.y;
                acc[i].z += p*vv.z; acc[i].w += p*vv.w;
            }
        }
        __syncthreads();
    }
    float inv = 1.f / sum;
    float* Cout = CTXg + ((size_t)(b*TT + t))*HH + h*64;
#pragma unroll
    for (int i = 0; i < 16; i++) {
        float4 a = acc[i];
        a.x*=inv; a.y*=inv; a.z*=inv; a.w*=inv;
        *(float4*)&Cout[i*4] = a;
    }
}

// ---------------- final fc: 16 (b,t) rows per block, thread = hidden unit ----------------
__global__ void __launch_bounds__(256) final_kernel(const float* __restrict__ W2,
                                                    const float* __restrict__ b2p,
                                                    float* __restrict__ out) {
    __shared__ float Ls[16][256];
    __shared__ float Cs[16][256];
    __shared__ float red[8][16];
    const int m0 = blockIdx.x * 16;
    const int tid = threadIdx.x;
#pragma unroll
    for (int j = 0; j < 4; j++) {
        int f = tid + j*256;                   // float4 index 0..1023
        int row = f >> 6, c = f & 63;
        *(float4*)&Ls[row][c*4] = *(const float4*)&Lg[(size_t)(m0+row)*256 + c*4];
        *(float4*)&Cs[row][c*4] = *(const float4*)&CTXg[(size_t)(m0+row)*256 + c*4];
    }
    __syncthreads();

    const int r = tid;
    float v[16];
    float bb = b1fw[r];
#pragma unroll
    for (int i = 0; i < 16; i++) v[i] = bb;
#pragma unroll 4
    for (int k = 0; k < 256; k++) {
        float w1 = W1aTw[k*256 + r];
        float wc = WcombTw[k*256 + r];
#pragma unroll
        for (int i = 0; i < 16; i++) v[i] += w1*Ls[i][k] + wc*Cs[i][k];
    }
    float w2 = W2[r];
#pragma unroll
    for (int i = 0; i < 16; i++) v[i] = w2 * fmaxf(v[i], 0.f);
#pragma unroll
    for (int off = 16; off > 0; off >>= 1)
#pragma unroll
        for (int i = 0; i < 16; i++) v[i] += __shfl_down_sync(0xffffffffu, v[i], off);
    int lane = tid & 31, wid = tid >> 5;
    if (lane == 0)
#pragma unroll
        for (int i = 0; i < 16; i++) red[wid][i] = v[i];
    __syncthreads();
    if (tid < 16) {
        float s = b2p[0];
#pragma unroll
        for (int w = 0; w < 8; w++) s += red[w][tid];
        out[m0 + tid] = s;
    }
}

// ---------------- launch ----------------
extern "C" void kernel_launch(void* const* d_in, const int* in_sizes, int n_in,
                              void* d_out, int out_size) {
    (void)in_sizes; (void)n_in; (void)out_size;
    const float* F     = (const float*)d_in[0];
    const float* Wih0  = (const float*)d_in[1];
    const float* Whh0  = (const float*)d_in[2];
    const float* bih0  = (const float*)d_in[3];
    const float* bhh0  = (const float*)d_in[4];
    const float* Wih1  = (const float*)d_in[5];
    const float* Whh1  = (const float*)d_in[6];
    const float* bih1  = (const float*)d_in[7];
    const float* bhh1  = (const float*)d_in[8];
    const float* Winp  = (const float*)d_in[9];
    const float* binp  = (const float*)d_in[10];
    const float* Wop   = (const float*)d_in[11];
    const float* bop   = (const float*)d_in[12];
    const float* W1    = (const float*)d_in[13];
    const float* b1    = (const float*)d_in[14];
    const float* W2    = (const float*)d_in[15];
    const float* b2    = (const float*)d_in[16];
    float* out = (float*)d_out;

    prep_pack<<<3724, 256>>>(Wih0, Whh0, bih0, bhh0, Wih1, Whh1, bih1, bhh1, W1);
    prep_wcomb<<<256, 256>>>(W1, Wop);
    prep_b1f<<<1, 256>>>(b1, bop, W1);
    scan_kernel<<<128, 256>>>(F, b1, W2, b2);
    qkv_kernel<<<dim3(1024, 6), 256>>>(Winp, binp);
    attn_kernel<<<dim3(512, 4), 256>>>();
    final_kernel<<<8192, 256>>>(W2, b2, out);
}

// round 3
// speedup vs baseline: 1.9504x; 1.9504x over previous
#include <cuda_runtime.h>
#include <cuda_fp16.h>
#include <math.h>

#define BATCH 512
#define TT    256
#define DD    32
#define HH    256
#define M_TOTAL (BATCH*TT)
#define PSTR  (BATCH*4*TT*64)

// ---------------- static device scratch ----------------
__device__ __half P0h[296*1024];    // [k8][1024][8] halves; k: 0..31 x, 32 pd, 33..39 zero, 40..295 h1
__device__ __half P1h[512*1024];    // [k8][1024][8]; k<256 Wih1(h1), k>=256 Whh1(h2)
__device__ float  PFf[256*256];     // [k8][256][8] floats; PF[k][r] = W1[r][k]+W1[r][256+k]
__device__ float  W1aTw[256*256];   // [k][r] = W1[r][k]
__device__ float  WcombTw[256*256]; // [m][r] = sum_j W1[r][256+j]*Wop[j][m]
__device__ float  b1fw[256];
__device__ float  Lg[M_TOTAL*HH];
__device__ float  CTXg[M_TOTAL*HH];
__device__ float  QKVg[3*PSTR];

__device__ __forceinline__ float sigf(float x) { return 1.f / (1.f + __expf(-x)); }
__device__ __forceinline__ float tanh_f(float x) {
    x = fmaxf(fminf(x, 30.f), -30.f);
    float z = __expf(-2.f * x);
    return (1.f - z) / (1.f + z);
}

// packed fp32x2 helpers
__device__ __forceinline__ void fma2(unsigned long long &acc, unsigned long long a, unsigned long long b) {
    asm("fma.rn.f32x2 %0, %1, %2, %0;" : "+l"(acc) : "l"(a), "l"(b));
}
__device__ __forceinline__ float2 unpack2(unsigned long long v) {
    float2 r; asm("mov.b64 {%0, %1}, %2;" : "=f"(r.x), "=f"(r.y) : "l"(v)); return r;
}
// 2 halves (packed in u32) -> packed f32x2 in b64
__device__ __forceinline__ unsigned long long h2tof2(unsigned int h) {
    unsigned long long r;
    asm("{\n\t.reg .b16 lo, hi;\n\t.reg .f32 fl, fh;\n\t"
        "mov.b32 {lo, hi}, %1;\n\t"
        "cvt.f32.f16 fl, lo;\n\t"
        "cvt.f32.f16 fh, hi;\n\t"
        "mov.b64 %0, {fl, fh};\n\t}\n"
        : "=l"(r) : "r"(h));
    return r;
}

// ---------------- prep ----------------
__global__ void prep_all(const float* __restrict__ Wih0, const float* __restrict__ Whh0,
                         const float* __restrict__ Wih1, const float* __restrict__ Whh1,
                         const float* __restrict__ W1) {
    int i = blockIdx.x * 256 + threadIdx.x;
    const int S0 = 296*1024;        // 303104
    const int S1 = S0 + 512*1024;   // 827392
    const int S2 = S1 + 65536;      // 892928
    const int S3 = S2 + 65536;      // 958464
    if (i < S0) {
        int jj = i & 7, j = (i >> 3) & 1023, k8 = i >> 13;
        int k = k8*8 + jj;
        float v = 0.f;
        if (k < 33) v = Wih0[j*33 + k];
        else if (k >= 40) v = Whh0[j*256 + (k-40)];
        P0h[i] = __float2half(v);
    } else if (i < S1) {
        int e = i - S0; int jj = e & 7, j = (e >> 3) & 1023, k8 = e >> 13;
        int k = k8*8 + jj;
        float v = (k < 256) ? Wih1[j*256 + k] : Whh1[j*256 + (k-256)];
        P1h[e] = __float2half(v);
    } else if (i < S2) {
        int e = i - S1; int jj = e & 7, r = (e >> 3) & 255, k8 = e >> 11;
        int k = k8*8 + jj;
        PFf[e] = W1[r*512 + k] + W1[r*512 + 256 + k];
    } else if (i < S3) {
        int e = i - S2; int k = e >> 8, r = e & 255;
        W1aTw[e] = W1[r*512 + k];
    }
}

__global__ void prep_wcomb(const float* __restrict__ W1, const float* __restrict__ Wop) {
    int r = blockIdx.x, m = threadIdx.x;
    float s = 0.f;
    for (int k = 0; k < 256; k++) s += W1[r*512 + 256 + k] * Wop[k*256 + m];
    WcombTw[m*256 + r] = s;
}

__global__ void prep_b1f(const float* __restrict__ b1, const float* __restrict__ bop,
                         const float* __restrict__ W1) {
    int r = threadIdx.x;
    float s = b1[r];
    for (int k = 0; k < 256; k++) s += bop[k] * W1[r*512 + 256 + k];
    b1fw[r] = s;
}

// ---------------- scan: 128 blocks x 1024 threads, 4 rows/block ----------------
#define ROWACC(A, PTR) { \
    const ulonglong2* _hp = (const ulonglong2*)(PTR); \
    ulonglong2 _hA = _hp[0], _hB = _hp[1]; \
    fma2(A, w0, _hA.x); fma2(A, w1, _hA.y); \
    fma2(A, w2_, _hB.x); fma2(A, w3, _hB.y); }

__global__ void __launch_bounds__(1024, 1) scan_kernel(
    const float* __restrict__ F,
    const float* __restrict__ bih0, const float* __restrict__ bhh0,
    const float* __restrict__ bih1, const float* __restrict__ bhh1,
    const float* __restrict__ b1, const float* __restrict__ W2,
    const float* __restrict__ b2p)
{
    __shared__ __align__(16) float in0[4][296];   // x(32)|pd|zeros(7)|h1(256)
    __shared__ __align__(16) float h2s[4][256];
    __shared__ float gs[4][1024];
    __shared__ float red[4][8];

    const int tid = threadIdx.x;
    const int j = tid;                   // gate-line (gate*256+n)
    const int rr = tid >> 8, n = tid & 255;  // activation/fc role
    const int b0 = blockIdx.x * 4;

    const float bias0 = bih0[j] + bhh0[j];
    const float bias1 = bih1[j] + bhh1[j];
    const float b1r = b1[n];
    const float w2r = W2[n];
    const float b2v = b2p[0];
    float c1 = 0.f, c2 = 0.f;

    for (int i = tid; i < 4*296; i += 1024) (&in0[0][0])[i] = 0.f;
    h2s[rr][n] = 0.f;
    __syncthreads();

    const uint4* P0v = (const uint4*)P0h;
    const uint4* P1v = (const uint4*)P1h;
    const ulonglong2* PFv = (const ulonglong2*)PFf;

    for (int t = 0; t < TT; t++) {
        if (tid < 128) {
            int r = tid >> 5, k = tid & 31;
            in0[r][k] = F[(size_t)(b0 + r)*(TT*DD) + t*DD + k];
        }
        __syncthreads();

        // ---- layer 0 gates (K=296, incl. x, pd, h1_{t-1}) ----
        {
            unsigned long long a0=0ull, a1=0ull, a2=0ull, a3=0ull;
#pragma unroll 2
            for (int g = 0; g < 37; g++) {
                uint4 w8 = P0v[g*1024 + j];
                unsigned long long w0 = h2tof2(w8.x);
                unsigned long long w1 = h2tof2(w8.y);
                unsigned long long w2_ = h2tof2(w8.z);
                unsigned long long w3 = h2tof2(w8.w);
                ROWACC(a0, &in0[0][g*8]);
                ROWACC(a1, &in0[1][g*8]);
                ROWACC(a2, &in0[2][g*8]);
                ROWACC(a3, &in0[3][g*8]);
            }
            float2 u;
            u = unpack2(a0); gs[0][j] = u.x + u.y + bias0;
            u = unpack2(a1); gs[1][j] = u.x + u.y + bias0;
            u = unpack2(a2); gs[2][j] = u.x + u.y + bias0;
            u = unpack2(a3); gs[3][j] = u.x + u.y + bias0;
        }
        __syncthreads();

        // ---- layer 0 activation (thread = (row rr, neuron n)) ----
        {
            float gi = gs[rr][n];
            float gf = gs[rr][256 + n];
            float gg = gs[rr][512 + n];
            float go = gs[rr][768 + n];
            c1 = sigf(gf)*c1 + sigf(gi)*tanh_f(gg);
            float h1v = sigf(go)*tanh_f(c1);
            in0[rr][40 + n] = h1v;
        }
        __syncthreads();

        // ---- layer 1 gates (K=512: h1_t then h2_{t-1}) ----
        {
            unsigned long long a0=0ull, a1=0ull, a2=0ull, a3=0ull;
#pragma unroll 2
            for (int g = 0; g < 32; g++) {
                uint4 w8 = P1v[g*1024 + j];
                unsigned long long w0 = h2tof2(w8.x);
                unsigned long long w1 = h2tof2(w8.y);
                unsigned long long w2_ = h2tof2(w8.z);
                unsigned long long w3 = h2tof2(w8.w);
                ROWACC(a0, &in0[0][40 + g*8]);
                ROWACC(a1, &in0[1][40 + g*8]);
                ROWACC(a2, &in0[2][40 + g*8]);
                ROWACC(a3, &in0[3][40 + g*8]);
            }
#pragma unroll 2
            for (int g = 32; g < 64; g++) {
                uint4 w8 = P1v[g*1024 + j];
                unsigned long long w0 = h2tof2(w8.x);
                unsigned long long w1 = h2tof2(w8.y);
                unsigned long long w2_ = h2tof2(w8.z);
                unsigned long long w3 = h2tof2(w8.w);
                ROWACC(a0, &h2s[0][(g-32)*8]);
                ROWACC(a1, &h2s[1][(g-32)*8]);
                ROWACC(a2, &h2s[2][(g-32)*8]);
                ROWACC(a3, &h2s[3][(g-32)*8]);
            }
            float2 u;
            u = unpack2(a0); gs[0][j] = u.x + u.y + bias1;
            u = unpack2(a1); gs[1][j] = u.x + u.y + bias1;
            u = unpack2(a2); gs[2][j] = u.x + u.y + bias1;
            u = unpack2(a3); gs[3][j] = u.x + u.y + bias1;
        }
        __syncthreads();

        // ---- layer 1 activation + store to Lg ----
        {
            float gi = gs[rr][n];
            float gf = gs[rr][256 + n];
            float gg = gs[rr][512 + n];
            float go = gs[rr][768 + n];
            c2 = sigf(gf)*c2 + sigf(gi)*tanh_f(gg);
            float h2v = sigf(go)*tanh_f(c2);
            h2s[rr][n] = h2v;
            Lg[(size_t)(b0 + rr)*(TT*HH) + t*HH + n] = h2v;
        }
        __syncthreads();

        // ---- fc -> pd (thread = (row rr, hidden n)) ----
        {
            unsigned long long acc = 0ull;
#pragma unroll 2
            for (int g = 0; g < 32; g++) {
                ulonglong2 wA = PFv[(g*256 + n)*2];
                ulonglong2 wB = PFv[(g*256 + n)*2 + 1];
                const ulonglong2* hp = (const ulonglong2*)&h2s[rr][g*8];
                ulonglong2 hA = hp[0], hB = hp[1];
                fma2(acc, wA.x, hA.x); fma2(acc, wA.y, hA.y);
                fma2(acc, wB.x, hB.x); fma2(acc, wB.y, hB.y);
            }
            float2 u = unpack2(acc);
            float v = u.x + u.y + b1r;
            float p = w2r * fmaxf(v, 0.f);
#pragma unroll
            for (int off = 16; off > 0; off >>= 1)
                p += __shfl_down_sync(0xffffffffu, p, off);
            if ((tid & 31) == 0) red[rr][(tid >> 5) & 7] = p;
        }
        __syncthreads();
        if (n == 0) {
            float s = b2v;
#pragma unroll
            for (int w = 0; w < 8; w++) s += red[rr][w];
            in0[rr][32] = s;   // pd feedback
        }
        __syncthreads();
    }
}

// ---------------- qkv GEMM ----------------
__global__ void __launch_bounds__(256) qkv_kernel(const float* __restrict__ Winp,
                                                  const float* __restrict__ binp) {
    __shared__ float As[16][128];
    __shared__ float Bs[16][128];
    const int m0 = blockIdx.x * 128;
    const int n0 = blockIdx.y * 128;
    const int tid = threadIdx.x;
    const int tx = tid & 15, ty = tid >> 4;
    float acc[8][8];
#pragma unroll
    for (int i = 0; i < 8; i++)
#pragma unroll
        for (int j = 0; j < 8; j++) acc[i][j] = 0.f;

    for (int k0 = 0; k0 < 256; k0 += 16) {
#pragma unroll
        for (int i = 0; i < 2; i++) {
            int idx = tid + i*256;
            int m = idx >> 2, q = idx & 3;
            float4 a = *(const float4*)&Lg[(size_t)(m0+m)*256 + k0 + q*4];
            As[q*4+0][m]=a.x; As[q*4+1][m]=a.y; As[q*4+2][m]=a.z; As[q*4+3][m]=a.w;
            float4 w = *(const float4*)&Winp[(size_t)(n0+m)*256 + k0 + q*4];
            Bs[q*4+0][m]=w.x; Bs[q*4+1][m]=w.y; Bs[q*4+2][m]=w.z; Bs[q*4+3][m]=w.w;
        }
        __syncthreads();
#pragma unroll
        for (int k = 0; k < 16; k++) {
            float a[8], b[8];
            *(float4*)&a[0] = *(float4*)&As[k][ty*8];
            *(float4*)&a[4] = *(float4*)&As[k][ty*8+4];
            *(float4*)&b[0] = *(float4*)&Bs[k][tx*8];
            *(float4*)&b[4] = *(float4*)&Bs[k][tx*8+4];
#pragma unroll
            for (int i = 0; i < 8; i++)
#pragma unroll
                for (int j = 0; j < 8; j++) acc[i][j] += a[i]*b[j];
        }
        __syncthreads();
    }

    int n_base = n0 + tx*8;
    float bi[8];
#pragma unroll
    for (int j = 0; j < 8; j++) bi[j] = binp[n_base + j];
    int part = n_base >> 8;
    int rem  = n_base & 255;
    int head = rem >> 6;
    int d0   = rem & 63;
#pragma unroll
    for (int i = 0; i < 8; i++) {
        int m = m0 + ty*8 + i;
        int bb = m >> 8, tt = m & 255;
        float* dst = QKVg + ((size_t)((part*BATCH + bb)*4 + head)*TT + tt)*64 + d0;
        float4 o0 = make_float4(acc[i][0]+bi[0], acc[i][1]+bi[1], acc[i][2]+bi[2], acc[i][3]+bi[3]);
        float4 o1 = make_float4(acc[i][4]+bi[4], acc[i][5]+bi[5], acc[i][6]+bi[6], acc[i][7]+bi[7]);
        *(float4*)&dst[0] = o0;
        *(float4*)&dst[4] = o1;
    }
}

// ---------------- attention ----------------
__global__ void __launch_bounds__(256) attn_kernel() {
    __shared__ float4 Ks[64][16];
    __shared__ float4 Vs[64][16];
    const int b = blockIdx.x, h = blockIdx.y;
    const int t = threadIdx.x;
    const float* Qb = QKVg + ((size_t)(b*4 + h))*TT*64;
    const float* Kb = Qb + PSTR;
    const float* Vb = Kb + PSTR;

    float4 q[16], acc[16];
#pragma unroll
    for (int i = 0; i < 16; i++) {
        q[i] = *(const float4*)&Qb[t*64 + i*4];
        acc[i] = make_float4(0.f, 0.f, 0.f, 0.f);
    }
    float sum = 0.f;

    for (int kc = 0; kc < 4; kc++) {
#pragma unroll
        for (int j = 0; j < 4; j++) {
            int f = t + j*256;
            int row = f >> 4, c = f & 15;
            Ks[row][c] = *(const float4*)&Kb[(size_t)(kc*64 + row)*64 + c*4];
            Vs[row][c] = *(const float4*)&Vb[(size_t)(kc*64 + row)*64 + c*4];
        }
        __syncthreads();
#pragma unroll 2
        for (int k = 0; k < 64; k++) {
            float s = 0.f;
#pragma unroll
            for (int i = 0; i < 16; i++) {
                float4 kv = Ks[k][i];
                s += q[i].x*kv.x + q[i].y*kv.y + q[i].z*kv.z + q[i].w*kv.w;
            }
            float p = __expf(s * 0.125f);
            sum += p;
#pragma unroll
            for (int i = 0; i < 16; i++) {
                float4 vv = Vs[k][i];
                acc[i].x += p*vv.x; acc[i].y += p*vv.y;
                acc[i].z += p*vv.z; acc[i].w += p*vv.w;
            }
        }
        __syncthreads();
    }
    float inv = 1.f / sum;
    float* Cout = CTXg + ((size_t)(b*TT + t))*HH + h*64;
#pragma unroll
    for (int i = 0; i < 16; i++) {
        float4 a = acc[i];
        a.x*=inv; a.y*=inv; a.z*=inv; a.w*=inv;
        *(float4*)&Cout[i*4] = a;
    }
}

// ---------------- final fc ----------------
__global__ void __launch_bounds__(256) final_kernel(const float* __restrict__ W2,
                                                    const float* __restrict__ b2p,
                                                    float* __restrict__ out) {
    __shared__ float Ls[16][256];
    __shared__ float Cs[16][256];
    __shared__ float red[8][16];
    const int m0 = blockIdx.x * 16;
    const int tid = threadIdx.x;
#pragma unroll
    for (int j = 0; j < 4; j++) {
        int f = tid + j*256;
        int row = f >> 6, c = f & 63;
        *(float4*)&Ls[row][c*4] = *(const float4*)&Lg[(size_t)(m0+row)*256 + c*4];
        *(float4*)&Cs[row][c*4] = *(const float4*)&CTXg[(size_t)(m0+row)*256 + c*4];
    }
    __syncthreads();

    const int r = tid;
    float v[16];
    float bb = b1fw[r];
#pragma unroll
    for (int i = 0; i < 16; i++) v[i] = bb;
#pragma unroll 4
    for (int k = 0; k < 256; k++) {
        float w1 = W1aTw[k*256 + r];
        float wc = WcombTw[k*256 + r];
#pragma unroll
        for (int i = 0; i < 16; i++) v[i] += w1*Ls[i][k] + wc*Cs[i][k];
    }
    float w2 = W2[r];
#pragma unroll
    for (int i = 0; i < 16; i++) v[i] = w2 * fmaxf(v[i], 0.f);
#pragma unroll
    for (int off = 16; off > 0; off >>= 1)
#pragma unroll
        for (int i = 0; i < 16; i++) v[i] += __shfl_down_sync(0xffffffffu, v[i], off);
    int lane = tid & 31, wid = tid >> 5;
    if (lane == 0)
#pragma unroll
        for (int i = 0; i < 16; i++) red[wid][i] = v[i];
    __syncthreads();
    if (tid < 16) {
        float s = b2p[0];
#pragma unroll
        for (int w = 0; w < 8; w++) s += red[w][tid];
        out[m0 + tid] = s;
    }
}

// ---------------- launch ----------------
extern "C" void kernel_launch(void* const* d_in, const int* in_sizes, int n_in,
                              void* d_out, int out_size) {
    (void)in_sizes; (void)n_in; (void)out_size;
    const float* F     = (const float*)d_in[0];
    const float* Wih0  = (const float*)d_in[1];
    const float* Whh0  = (const float*)d_in[2];
    const float* bih0  = (const float*)d_in[3];
    const float* bhh0  = (const float*)d_in[4];
    const float* Wih1  = (const float*)d_in[5];
    const float* Whh1  = (const float*)d_in[6];
    const float* bih1  = (const float*)d_in[7];
    const float* bhh1  = (const float*)d_in[8];
    const float* Winp  = (const float*)d_in[9];
    const float* binp  = (const float*)d_in[10];
    const float* Wop   = (const float*)d_in[11];
    const float* bop   = (const float*)d_in[12];
    const float* W1    = (const float*)d_in[13];
    const float* b1    = (const float*)d_in[14];
    const float* W2    = (const float*)d_in[15];
    const float* b2    = (const float*)d_in[16];
    float* out = (float*)d_out;

    prep_all<<<3744, 256>>>(Wih0, Whh0, Wih1, Whh1, W1);
    prep_wcomb<<<256, 256>>>(W1, Wop);
    prep_b1f<<<1, 256>>>(b1, bop, W1);
    scan_kernel<<<128, 1024>>>(F, bih0, bhh0, bih1, bhh1, b1, W2, b2);
    qkv_kernel<<<dim3(1024, 6), 256>>>(Winp, binp);
    attn_kernel<<<dim3(512, 4), 256>>>();
    final_kernel<<<8192, 256>>>(W2, b2, out);
}

// round 5
// speedup vs baseline: 2.9871x; 1.5316x over previous
#include <cuda_runtime.h>
#include <cuda_fp16.h>
#include <math.h>

#define BATCH 512
#define TT    256
#define DD    32
#define HH    256
#define M_TOTAL (BATCH*TT)
#define PSTR  (BATCH*4*TT*64)

// scan config
#define NBLK 32
#define RPB  16
#define K0T  19      // layer0 K=304: 0..31 x, 32 pd, 33..47 zero, 48..303 h1
#define K1T  32      // layer1 K=512: h1(0..255), h2(256..511)
#define KFT  16      // fc K=256 (h2)
#define S0   312     // actT0 row stride (halves)
#define S1   520     // act1 row stride (halves)
#define GSTR 17      // gates buffer row stride (floats)

// ---------------- static device scratch ----------------
__device__ __half W0f[K0T*64*256];   // layer0 A fragments [(mt*K0T+kt)*256 + lane*8 + q]
__device__ __half W1f[K1T*64*256];
__device__ __half WFf[KFT*16*256];
__device__ float  W1aTw[256*256];    // [k][r] = W1[r][k]
__device__ float  WcombTw[256*256];  // [m][r] = sum_j W1[r][256+j]*Wop[j][m]
__device__ float  b1fw[256];
__device__ float  Lg[M_TOTAL*HH];
__device__ float  CTXg[M_TOTAL*HH];
__device__ float  QKVg[3*PSTR];

__device__ __forceinline__ float sigf(float x) { return 1.f / (1.f + __expf(-x)); }
__device__ __forceinline__ float tanh_f(float x) {
    x = fmaxf(fminf(x, 30.f), -30.f);
    float z = __expf(-2.f * x);
    return (1.f - z) / (1.f + z);
}

// ---------------- prep: fragment packing ----------------
__global__ void prep_frag(const float* __restrict__ Wih0, const float* __restrict__ Whh0,
                          const float* __restrict__ Wih1, const float* __restrict__ Whh1,
                          const float* __restrict__ W1) {
    int i = blockIdx.x * 256 + threadIdx.x;
    const int E0 = K0T*64*256;          // 311296
    const int E1 = E0 + K1T*64*256;     // 835584
    const int E2 = E1 + KFT*16*256;     // 901120
    const int E3 = E2 + 65536;          // 966656
    if (i < E0) {
        int q = i & 7, lane = (i >> 3) & 31, tile = i >> 8;
        int mt = tile / K0T, kt = tile - mt * K0T;
        int r = lane >> 2, c = lane & 3;
        int dm = r + ((q >> 1) & 1) * 8;
        int dk = 2*c + (q & 1) + ((q >= 4) ? 8 : 0);
        int m = mt*16 + dm, k = kt*16 + dk;
        float v = 0.f;
        if (k < 33) v = Wih0[m*33 + k];
        else if (k >= 48) v = Whh0[m*256 + (k - 48)];
        W0f[i] = __float2half(v);
    } else if (i < E1) {
        int e = i - E0;
        int q = e & 7, lane = (e >> 3) & 31, tile = e >> 8;
        int mt = tile >> 5, kt = tile & 31;
        int r = lane >> 2, c = lane & 3;
        int dm = r + ((q >> 1) & 1) * 8;
        int dk = 2*c + (q & 1) + ((q >= 4) ? 8 : 0);
        int m = mt*16 + dm, k = kt*16 + dk;
        float v = (k < 256) ? Wih1[m*256 + k] : Whh1[m*256 + (k - 256)];
        W1f[e] = __float2half(v);
    } else if (i < E2) {
        int e = i - E1;
        int q = e & 7, lane = (e >> 3) & 31, tile = e >> 8;
        int mt = tile >> 4, kt = tile & 15;
        int r = lane >> 2, c = lane & 3;
        int dm = r + ((q >> 1) & 1) * 8;
        int dk = 2*c + (q & 1) + ((q >= 4) ? 8 : 0);
        int m = mt*16 + dm, k = kt*16 + dk;
        WFf[e] = __float2half(W1[m*512 + k] + W1[m*512 + 256 + k]);
    } else if (i < E3) {
        int e = i - E2; int k = e >> 8, r = e & 255;
        W1aTw[e] = W1[r*512 + k];
    }
}

__global__ void prep_wcomb(const float* __restrict__ W1, const float* __restrict__ Wop) {
    int r = blockIdx.x, m = threadIdx.x;
    float s = 0.f;
    for (int k = 0; k < 256; k++) s += W1[r*512 + 256 + k] * Wop[k*256 + m];
    WcombTw[m*256 + r] = s;
}

__global__ void prep_b1f(const float* __restrict__ b1, const float* __restrict__ bop,
                         const float* __restrict__ W1) {
    int r = threadIdx.x;
    float s = b1[r];
    for (int k = 0; k < 256; k++) s += bop[k] * W1[r*512 + 256 + k];
    b1fw[r] = s;
}

// ---------------- mma helpers ----------------
__device__ __forceinline__ void mma_op(float* c, unsigned a0, unsigned a1, unsigned a2, unsigned a3,
                                       unsigned b0, unsigned b1) {
    asm volatile("mma.sync.aligned.m16n8k16.row.col.f32.f16.f16.f32 "
        "{%0,%1,%2,%3}, {%4,%5,%6,%7}, {%8,%9}, {%0,%1,%2,%3};"
        : "+f"(c[0]), "+f"(c[1]), "+f"(c[2]), "+f"(c[3])
        : "r"(a0), "r"(a1), "r"(a2), "r"(a3), "r"(b0), "r"(b1));
}

template<int KT>
__device__ __forceinline__ void gemm_warp(const __half* __restrict__ Wg, int mt,
                                          const __half* __restrict__ B, int bstr,
                                          float* __restrict__ gs, int lane) {
    const int r = lane >> 2, c2 = (lane & 3) * 2;
    float acc0[4] = {0.f,0.f,0.f,0.f};
    float acc1[4] = {0.f,0.f,0.f,0.f};
    const uint4* Ap = (const uint4*)Wg + (size_t)mt*KT*32 + lane;
    const __half* B0 = B + r*bstr + c2;
    const __half* B1 = B + (8 + r)*bstr + c2;
#pragma unroll
    for (int kt = 0; kt < KT; kt++) {
        uint4 A = Ap[kt*32];
        unsigned b00 = *(const unsigned*)(B0 + kt*16);
        unsigned b01 = *(const unsigned*)(B0 + kt*16 + 8);
        unsigned b10 = *(const unsigned*)(B1 + kt*16);
        unsigned b11 = *(const unsigned*)(B1 + kt*16 + 8);
        mma_op(acc0, A.x, A.y, A.z, A.w, b00, b01);
        mma_op(acc1, A.x, A.y, A.z, A.w, b10, b11);
    }
    const int m0 = mt*16;
    float* g0 = gs + (m0 + r)*GSTR + c2;
    float* g1 = gs + (m0 + 8 + r)*GSTR + c2;
    g0[0] = acc0[0]; g0[1] = acc0[1];
    g1[0] = acc0[2]; g1[1] = acc0[3];
    g0[8] = acc1[0]; g0[9] = acc1[1];
    g1[8] = acc1[2]; g1[9] = acc1[3];
}

// ---------------- scan: 32 blocks x 1024 threads, 16 rows/block ----------------
extern __shared__ char smem_raw[];

__global__ void __launch_bounds__(1024, 1) scan_kernel(
    const float* __restrict__ F,
    const float* __restrict__ bih0, const float* __restrict__ bhh0,
    const float* __restrict__ bih1, const float* __restrict__ bhh1,
    const float* __restrict__ b1, const float* __restrict__ W2,
    const float* __restrict__ b2p)
{
    float*  gs  = (float*)smem_raw;                 // 1024*17 f32   = 69632 B
    __half* a0s = (__half*)(smem_raw + 69632);      // 16*312 halves =  9984 B
    __half* a1s = (__half*)(smem_raw + 79616);      // 16*520 halves = 16640 B
    float*  red = (float*)(smem_raw + 96256);       // 32*4 f32      =   512 B

    const int tid = threadIdx.x;
    const int w = tid >> 5, lane = tid & 31;
    const int n = tid & 255, rg = tid >> 8;
    const int b0r = blockIdx.x * RPB;

    float bi0[4], bi1[4];
#pragma unroll
    for (int g = 0; g < 4; g++) {
        bi0[g] = bih0[g*256 + n] + bhh0[g*256 + n];
        bi1[g] = bih1[g*256 + n] + bhh1[g*256 + n];
    }
    const float b1n = b1[n];
    const float w2n = W2[n];
    const float b2v = b2p[0];
    float c1v[4] = {0.f,0.f,0.f,0.f};
    float c2v[4] = {0.f,0.f,0.f,0.f};

    const __half hz = __float2half(0.f);
    for (int i = tid; i < 16*S0; i += 1024) a0s[i] = hz;
    for (int i = tid; i < 16*S1; i += 1024) a1s[i] = hz;
    __syncthreads();

    for (int t = 0; t < TT; t++) {
        // stage x_t (fp16)
        if (tid < 512) {
            int row = tid >> 5, kx = tid & 31;
            a0s[row*S0 + kx] = __float2half(F[(size_t)(b0r + row)*(TT*DD) + t*DD + kx]);
        }
        __syncthreads();

        // layer0 gates
        gemm_warp<K0T>(W0f, 2*w,     a0s, S0, gs, lane);
        gemm_warp<K0T>(W0f, 2*w + 1, a0s, S0, gs, lane);
        __syncthreads();

        // layer0 activation
#pragma unroll
        for (int j = 0; j < 4; j++) {
            int row = rg*4 + j;
            float gi = gs[(      n)*GSTR + row] + bi0[0];
            float gf = gs[(256 + n)*GSTR + row] + bi0[1];
            float gg = gs[(512 + n)*GSTR + row] + bi0[2];
            float go = gs[(768 + n)*GSTR + row] + bi0[3];
            c1v[j] = sigf(gf)*c1v[j] + sigf(gi)*tanh_f(gg);
            float h1 = sigf(go)*tanh_f(c1v[j]);
            __half hh = __float2half(h1);
            a0s[row*S0 + 48 + n] = hh;     // for layer0 GEMM next step
            a1s[row*S1 + n]      = hh;     // for layer1 GEMM this step
        }
        __syncthreads();

        // layer1 gates
        gemm_warp<K1T>(W1f, 2*w,     a1s, S1, gs, lane);
        gemm_warp<K1T>(W1f, 2*w + 1, a1s, S1, gs, lane);
        __syncthreads();

        // layer1 activation + Lg store
#pragma unroll
        for (int j = 0; j < 4; j++) {
            int row = rg*4 + j;
            float gi = gs[(      n)*GSTR + row] + bi1[0];
            float gf = gs[(256 + n)*GSTR + row] + bi1[1];
            float gg = gs[(512 + n)*GSTR + row] + bi1[2];
            float go = gs[(768 + n)*GSTR + row] + bi1[3];
            c2v[j] = sigf(gf)*c2v[j] + sigf(gi)*tanh_f(gg);
            float h2 = sigf(go)*tanh_f(c2v[j]);
            a1s[row*S1 + 256 + n] = __float2half(h2);
            Lg[(size_t)(b0r + row)*(TT*HH) + t*HH + n] = h2;
        }
        __syncthreads();

        // fc hidden GEMM (warps 0..15)
        if (w < 16) gemm_warp<KFT>(WFf, w, a1s + 256, S1, gs, lane);
        __syncthreads();

        // pd reduce
        {
            float v[4];
#pragma unroll
            for (int j = 0; j < 4; j++) {
                int row = rg*4 + j;
                float hv = gs[n*GSTR + row] + b1n;
                v[j] = w2n * fmaxf(hv, 0.f);
            }
#pragma unroll
            for (int off = 16; off > 0; off >>= 1)
#pragma unroll
                for (int j = 0; j < 4; j++) v[j] += __shfl_down_sync(0xffffffffu, v[j], off);
            if (lane == 0) {
#pragma unroll
                for (int j = 0; j < 4; j++) red[w*4 + j] = v[j];
            }
        }
        __syncthreads();
        if (tid < 16) {
            int row = tid, rgr = row >> 2, jr = row & 3;
            float s = b2v;
#pragma unroll
            for (int ww = 0; ww < 8; ww++) s += red[(rgr*8 + ww)*4 + jr];
            a0s[row*S0 + 32] = __float2half(s);   // pd feedback for t+1
        }
        __syncthreads();
    }
}

// ---------------- qkv GEMM ----------------
__global__ void __launch_bounds__(256) qkv_kernel(const float* __restrict__ Winp,
                                                  const float* __restrict__ binp) {
    __shared__ float As[16][128];
    __shared__ float Bs[16][128];
    const int m0 = blockIdx.x * 128;
    const int n0 = blockIdx.y * 128;
    const int tid = threadIdx.x;
    const int tx = tid & 15, ty = tid >> 4;
    float acc[8][8];
#pragma unroll
    for (int i = 0; i < 8; i++)
#pragma unroll
        for (int j = 0; j < 8; j++) acc[i][j] = 0.f;

    for (int k0 = 0; k0 < 256; k0 += 16) {
#pragma unroll
        for (int i = 0; i < 2; i++) {
            int idx = tid + i*256;
            int m = idx >> 2, q = idx & 3;
            float4 a = *(const float4*)&Lg[(size_t)(m0+m)*256 + k0 + q*4];
            As[q*4+0][m]=a.x; As[q*4+1][m]=a.y; As[q*4+2][m]=a.z; As[q*4+3][m]=a.w;
            float4 w = *(const float4*)&Winp[(size_t)(n0+m)*256 + k0 + q*4];
            Bs[q*4+0][m]=w.x; Bs[q*4+1][m]=w.y; Bs[q*4+2][m]=w.z; Bs[q*4+3][m]=w.w;
        }
        __syncthreads();
#pragma unroll
        for (int k = 0; k < 16; k++) {
            float a[8], b[8];
            *(float4*)&a[0] = *(float4*)&As[k][ty*8];
            *(float4*)&a[4] = *(float4*)&As[k][ty*8+4];
            *(float4*)&b[0] = *(float4*)&Bs[k][tx*8];
            *(float4*)&b[4] = *(float4*)&Bs[k][tx*8+4];
#pragma unroll
            for (int i = 0; i < 8; i++)
#pragma unroll
                for (int j = 0; j < 8; j++) acc[i][j] += a[i]*b[j];
        }
        __syncthreads();
    }

    int n_base = n0 + tx*8;
    float bi[8];
#pragma unroll
    for (int j = 0; j < 8; j++) bi[j] = binp[n_base + j];
    int part = n_base >> 8;
    int rem  = n_base & 255;
    int head = rem >> 6;
    int d0   = rem & 63;
#pragma unroll
    for (int i = 0; i < 8; i++) {
        int m = m0 + ty*8 + i;
        int bb = m >> 8, tt = m & 255;
        float* dst = QKVg + ((size_t)((part*BATCH + bb)*4 + head)*TT + tt)*64 + d0;
        float4 o0 = make_float4(acc[i][0]+bi[0], acc[i][1]+bi[1], acc[i][2]+bi[2], acc[i][3]+bi[3]);
        float4 o1 = make_float4(acc[i][4]+bi[4], acc[i][5]+bi[5], acc[i][6]+bi[6], acc[i][7]+bi[7]);
        *(float4*)&dst[0] = o0;
        *(float4*)&dst[4] = o1;
    }
}

// ---------------- attention ----------------
__global__ void __launch_bounds__(256) attn_kernel() {
    __shared__ float4 Ks[64][16];
    __shared__ float4 Vs[64][16];
    const int b = blockIdx.x, h = blockIdx.y;
    const int t = threadIdx.x;
    const float* Qb = QKVg + ((size_t)(b*4 + h))*TT*64;
    const float* Kb = Qb + PSTR;
    const float* Vb = Kb + PSTR;

    float4 q[16], acc[16];
#pragma unroll
    for (int i = 0; i < 16; i++) {
        q[i] = *(const float4*)&Qb[t*64 + i*4];
        acc[i] = make_float4(0.f, 0.f, 0.f, 0.f);
    }
    float sum = 0.f;

    for (int kc = 0; kc < 4; kc++) {
#pragma unroll
        for (int j = 0; j < 4; j++) {
            int f = t + j*256;
            int row = f >> 4, c = f & 15;
            Ks[row][c] = *(const float4*)&Kb[(size_t)(kc*64 + row)*64 + c*4];
            Vs[row][c] = *(const float4*)&Vb[(size_t)(kc*64 + row)*64 + c*4];
        }
        __syncthreads();
#pragma unroll 2
        for (int k = 0; k < 64; k++) {
            float s = 0.f;
#pragma unroll
            for (int i = 0; i < 16; i++) {
                float4 kv = Ks[k][i];
                s += q[i].x*kv.x + q[i].y*kv.y + q[i].z*kv.z + q[i].w*kv.w;
            }
            float p = __expf(s * 0.125f);
            sum += p;
#pragma unroll
            for (int i = 0; i < 16; i++) {
                float4 vv = Vs[k][i];
                acc[i].x += p*vv.x; acc[i].y += p*vv.y;
                acc[i].z += p*vv.z; acc[i].w += p*vv.w;
            }
        }
        __syncthreads();
    }
    float inv = 1.f / sum;
    float* Cout = CTXg + ((size_t)(b*TT + t))*HH + h*64;
#pragma unroll
    for (int i = 0; i < 16; i++) {
        float4 a = acc[i];
        a.x*=inv; a.y*=inv; a.z*=inv; a.w*=inv;
        *(float4*)&Cout[i*4] = a;
    }
}

// ---------------- final fc ----------------
__global__ void __launch_bounds__(256) final_kernel(const float* __restrict__ W2,
                                                    const float* __restrict__ b2p,
                                                    float* __restrict__ out) {
    __shared__ float Ls[16][256];
    __shared__ float Cs[16][256];
    __shared__ float red[8][16];
    const int m0 = blockIdx.x * 16;
    const int tid = threadIdx.x;
#pragma unroll
    for (int j = 0; j < 4; j++) {
        int f = tid + j*256;
        int row = f >> 6, c = f & 63;
        *(float4*)&Ls[row][c*4] = *(const float4*)&Lg[(size_t)(m0+row)*256 + c*4];
        *(float4*)&Cs[row][c*4] = *(const float4*)&CTXg[(size_t)(m0+row)*256 + c*4];
    }
    __syncthreads();

    const int r = tid;
    float v[16];
    float bb = b1fw[r];
#pragma unroll
    for (int i = 0; i < 16; i++) v[i] = bb;
#pragma unroll 4
    for (int k = 0; k < 256; k++) {
        float w1 = W1aTw[k*256 + r];
        float wc = WcombTw[k*256 + r];
#pragma unroll
        for (int i = 0; i < 16; i++) v[i] += w1*Ls[i][k] + wc*Cs[i][k];
    }
    float w2 = W2[r];
#pragma unroll
    for (int i = 0; i < 16; i++) v[i] = w2 * fmaxf(v[i], 0.f);
#pragma unroll
    for (int off = 16; off > 0; off >>= 1)
#pragma unroll
        for (int i = 0; i < 16; i++) v[i] += __shfl_down_sync(0xffffffffu, v[i], off);
    int lane = tid & 31, wid = tid >> 5;
    if (lane == 0)
#pragma unroll
        for (int i = 0; i < 16; i++) red[wid][i] = v[i];
    __syncthreads();
    if (tid < 16) {
        float s = b2p[0];
#pragma unroll
        for (int w = 0; w < 8; w++) s += red[w][tid];
        out[m0 + tid] = s;
    }
}

// ---------------- launch ----------------
extern "C" void kernel_launch(void* const* d_in, const int* in_sizes, int n_in,
                              void* d_out, int out_size) {
    (void)in_sizes; (void)n_in; (void)out_size;
    const float* F     = (const float*)d_in[0];
    const float* Wih0  = (const float*)d_in[1];
    const float* Whh0  = (const float*)d_in[2];
    const float* bih0  = (const float*)d_in[3];
    const float* bhh0  = (const float*)d_in[4];
    const float* Wih1  = (const float*)d_in[5];
    const float* Whh1  = (const float*)d_in[6];
    const float* bih1  = (const float*)d_in[7];
    const float* bhh1  = (const float*)d_in[8];
    const float* Winp  = (const float*)d_in[9];
    const float* binp  = (const float*)d_in[10];
    const float* Wop   = (const float*)d_in[11];
    const float* bop   = (const float*)d_in[12];
    const float* W1    = (const float*)d_in[13];
    const float* b1    = (const float*)d_in[14];
    const float* W2    = (const float*)d_in[15];
    const float* b2    = (const float*)d_in[16];
    float* out = (float*)d_out;

    const int SMEM_BYTES = 96768;
    cudaFuncSetAttribute(scan_kernel, cudaFuncAttributeMaxDynamicSharedMemorySize, SMEM_BYTES);

    prep_frag<<<3776, 256>>>(Wih0, Whh0, Wih1, Whh1, W1);
    prep_wcomb<<<256, 256>>>(W1, Wop);
    prep_b1f<<<1, 256>>>(b1, bop, W1);
    scan_kernel<<<NBLK, 1024, SMEM_BYTES>>>(F, bih0, bhh0, bih1, bhh1, b1, W2, b2);
    qkv_kernel<<<dim3(1024, 6), 256>>>(Winp, binp);
    attn_kernel<<<dim3(512, 4), 256>>>();
    final_kernel<<<8192, 256>>>(W2, b2, out);
}

// round 7
// speedup vs baseline: 3.0476x; 1.0203x over previous
#include <cuda_runtime.h>
#include <cuda_fp16.h>
#include <math.h>

#define BATCH 512
#define TT    256
#define DD    32
#define HH    256
#define M_TOTAL (BATCH*TT)
#define PSTR  (BATCH*4*TT*64)

// scan config
#define NBLK 32
#define RPB  16
#define K0T  19
#define K1T  32
#define KFT  16
#define S0   312
#define S1   520
#define GSTR 17

// ---------------- static device scratch ----------------
__device__ __half W0f[K0T*64*256];
__device__ __half W1f[K1T*64*256];
__device__ __half WFf[KFT*16*256];
__device__ float  W1aTw[256*256];    // [k][r] = W1[r][k]
__device__ float  WcombTw[256*256];  // [m][r] = sum_j W1[r][256+j]*Wop[j][m]
__device__ float  b1fw[256];
__device__ float  Lg[M_TOTAL*HH];
__device__ float  CTXg[M_TOTAL*HH];
__device__ float  QKVg[3*PSTR];

__device__ __forceinline__ float sigf(float x) { return 1.f / (1.f + __expf(-x)); }
__device__ __forceinline__ float tanh_f(float x) {
    x = fmaxf(fminf(x, 30.f), -30.f);
    float z = __expf(-2.f * x);
    return (1.f - z) / (1.f + z);
}

__device__ __forceinline__ void ldsm4(unsigned &r0, unsigned &r1, unsigned &r2, unsigned &r3, unsigned addr) {
    asm volatile("ldmatrix.sync.aligned.m8n8.x4.shared.b16 {%0,%1,%2,%3}, [%4];"
                 : "=r"(r0),"=r"(r1),"=r"(r2),"=r"(r3) : "r"(addr));
}
__device__ __forceinline__ void mma_op(float* c, unsigned a0, unsigned a1, unsigned a2, unsigned a3,
                                       unsigned b0, unsigned b1) {
    asm volatile("mma.sync.aligned.m16n8k16.row.col.f32.f16.f16.f32 "
        "{%0,%1,%2,%3}, {%4,%5,%6,%7}, {%8,%9}, {%0,%1,%2,%3};"
        : "+f"(c[0]), "+f"(c[1]), "+f"(c[2]), "+f"(c[3])
        : "r"(a0), "r"(a1), "r"(a2), "r"(a3), "r"(b0), "r"(b1));
}

// ---------------- prep: fragment packing (identical to R5) ----------------
__global__ void prep_frag(const float* __restrict__ Wih0, const float* __restrict__ Whh0,
                          const float* __restrict__ Wih1, const float* __restrict__ Whh1,
                          const float* __restrict__ W1) {
    int i = blockIdx.x * 256 + threadIdx.x;
    const int E0 = K0T*64*256;          // 311296
    const int E1 = E0 + K1T*64*256;     // 835584
    const int E2 = E1 + KFT*16*256;     // 901120
    const int E3 = E2 + 65536;          // 966656
    if (i < E0) {
        int q = i & 7, lane = (i >> 3) & 31, tile = i >> 8;
        int mt = tile / K0T, kt = tile - mt * K0T;
        int r = lane >> 2, c = lane & 3;
        int dm = r + ((q >> 1) & 1) * 8;
        int dk = 2*c + (q & 1) + ((q >= 4) ? 8 : 0);
        int m = mt*16 + dm, k = kt*16 + dk;
        float v = 0.f;
        if (k < 33) v = Wih0[m*33 + k];
        else if (k >= 48) v = Whh0[m*256 + (k - 48)];
        W0f[i] = __float2half(v);
    } else if (i < E1) {
        int e = i - E0;
        int q = e & 7, lane = (e >> 3) & 31, tile = e >> 8;
        int mt = tile >> 5, kt = tile & 31;
        int r = lane >> 2, c = lane & 3;
        int dm = r + ((q >> 1) & 1) * 8;
        int dk = 2*c + (q & 1) + ((q >= 4) ? 8 : 0);
        int m = mt*16 + dm, k = kt*16 + dk;
        float v = (k < 256) ? Wih1[m*256 + k] : Whh1[m*256 + (k - 256)];
        W1f[e] = __float2half(v);
    } else if (i < E2) {
        int e = i - E1;
        int q = e & 7, lane = (e >> 3) & 31, tile = e >> 8;
        int mt = tile >> 4, kt = tile & 15;
        int r = lane >> 2, c = lane & 3;
        int dm = r + ((q >> 1) & 1) * 8;
        int dk = 2*c + (q & 1) + ((q >= 4) ? 8 : 0);
        int m = mt*16 + dm, k = kt*16 + dk;
        WFf[e] = __float2half(W1[m*512 + k] + W1[m*512 + 256 + k]);
    } else if (i < E3) {
        int e = i - E2; int k = e >> 8, r = e & 255;
        W1aTw[e] = W1[r*512 + k];
    }
}

__global__ void prep_wcomb(const float* __restrict__ W1, const float* __restrict__ Wop) {
    int r = blockIdx.x, m = threadIdx.x;
    float s = 0.f;
    for (int k = 0; k < 256; k++) s += W1[r*512 + 256 + k] * Wop[k*256 + m];
    WcombTw[m*256 + r] = s;
}

__global__ void prep_b1f(const float* __restrict__ b1, const float* __restrict__ bop,
                         const float* __restrict__ W1) {
    int r = threadIdx.x;
    float s = b1[r];
    for (int k = 0; k < 256; k++) s += bop[k] * W1[r*512 + 256 + k];
    b1fw[r] = s;
}

// ---------------- scan warp GEMM (B via ldmatrix — the ONE change vs R5) ----------------
template<int KT>
__device__ __forceinline__ void gemm_warp(const __half* __restrict__ Wg, int mt,
                                          unsigned actb, int bstr,
                                          float* __restrict__ gs, int lane) {
    const int r = lane >> 2, c2 = (lane & 3) * 2;
    float acc0[4] = {0.f,0.f,0.f,0.f};
    float acc1[4] = {0.f,0.f,0.f,0.f};
    const uint4* Ap = (const uint4*)Wg + (size_t)mt*KT*32 + lane;
    const int brow = (lane & 7) + ((lane >> 4) << 3);
    const int bkoff = ((lane >> 3) & 1) * 8;
    const unsigned baddr = actb + (unsigned)((brow*bstr + bkoff) * 2);
#pragma unroll
    for (int kt = 0; kt < KT; kt++) {
        uint4 A = Ap[kt*32];
        unsigned b00, b01, b10, b11;
        ldsm4(b00, b01, b10, b11, baddr + kt*32);
        mma_op(acc0, A.x, A.y, A.z, A.w, b00, b01);
        mma_op(acc1, A.x, A.y, A.z, A.w, b10, b11);
    }
    const int m0 = mt*16;
    float* g0 = gs + (m0 + r)*GSTR + c2;
    float* g1 = gs + (m0 + 8 + r)*GSTR + c2;
    g0[0] = acc0[0]; g0[1] = acc0[1];
    g1[0] = acc0[2]; g1[1] = acc0[3];
    g0[8] = acc1[0]; g0[9] = acc1[1];
    g1[8] = acc1[2]; g1[9] = acc1[3];
}

// ---------------- scan: 32 blocks x 1024 threads, 16 rows/block ----------------
extern __shared__ char smem_raw[];

__global__ void __launch_bounds__(1024, 1) scan_kernel(
    const float* __restrict__ F,
    const float* __restrict__ bih0, const float* __restrict__ bhh0,
    const float* __restrict__ bih1, const float* __restrict__ bhh1,
    const float* __restrict__ b1, const float* __restrict__ W2,
    const float* __restrict__ b2p)
{
    float*  gs  = (float*)smem_raw;                 // 1024*17 f32
    __half* a0s = (__half*)(smem_raw + 69632);      // 16*312
    __half* a1s = (__half*)(smem_raw + 79616);      // 16*520
    float*  red = (float*)(smem_raw + 96256);       // 32*4

    const int tid = threadIdx.x;
    const int w = tid >> 5, lane = tid & 31;
    const int n = tid & 255, rg = tid >> 8;
    const int b0r = blockIdx.x * RPB;

    const unsigned a0b = (unsigned)__cvta_generic_to_shared(a0s);
    const unsigned a1b = (unsigned)__cvta_generic_to_shared(a1s);

    float bi0[4], bi1[4];
#pragma unroll
    for (int g = 0; g < 4; g++) {
        bi0[g] = bih0[g*256 + n] + bhh0[g*256 + n];
        bi1[g] = bih1[g*256 + n] + bhh1[g*256 + n];
    }
    const float b1n = b1[n];
    const float w2n = W2[n];
    const float b2v = b2p[0];
    float c1v[4] = {0.f,0.f,0.f,0.f};
    float c2v[4] = {0.f,0.f,0.f,0.f};

    const __half hz = __float2half(0.f);
    for (int i = tid; i < 16*S0; i += 1024) a0s[i] = hz;
    for (int i = tid; i < 16*S1; i += 1024) a1s[i] = hz;
    __syncthreads();

    for (int t = 0; t < TT; t++) {
        if (tid < 512) {
            int row = tid >> 5, kx = tid & 31;
            a0s[row*S0 + kx] = __float2half(F[(size_t)(b0r + row)*(TT*DD) + t*DD + kx]);
        }
        __syncthreads();

        gemm_warp<K0T>(W0f, 2*w,     a0b, S0, gs, lane);
        gemm_warp<K0T>(W0f, 2*w + 1, a0b, S0, gs, lane);
        __syncthreads();

#pragma unroll
        for (int j = 0; j < 4; j++) {
            int row = rg*4 + j;
            float gi = gs[(      n)*GSTR + row] + bi0[0];
            float gf = gs[(256 + n)*GSTR + row] + bi0[1];
            float gg = gs[(512 + n)*GSTR + row] + bi0[2];
            float go = gs[(768 + n)*GSTR + row] + bi0[3];
            c1v[j] = sigf(gf)*c1v[j] + sigf(gi)*tanh_f(gg);
            float h1 = sigf(go)*tanh_f(c1v[j]);
            __half hh = __float2half(h1);
            a0s[row*S0 + 48 + n] = hh;
            a1s[row*S1 + n]      = hh;
        }
        __syncthreads();

        gemm_warp<K1T>(W1f, 2*w,     a1b, S1, gs, lane);
        gemm_warp<K1T>(W1f, 2*w + 1, a1b, S1, gs, lane);
        __syncthreads();

#pragma unroll
        for (int j = 0; j < 4; j++) {
            int row = rg*4 + j;
            float gi = gs[(      n)*GSTR + row] + bi1[0];
            float gf = gs[(256 + n)*GSTR + row] + bi1[1];
            float gg = gs[(512 + n)*GSTR + row] + bi1[2];
            float go = gs[(768 + n)*GSTR + row] + bi1[3];
            c2v[j] = sigf(gf)*c2v[j] + sigf(gi)*tanh_f(gg);
            float h2 = sigf(go)*tanh_f(c2v[j]);
            a1s[row*S1 + 256 + n] = __float2half(h2);
            Lg[(size_t)(b0r + row)*(TT*HH) + t*HH + n] = h2;
        }
        __syncthreads();

        if (w < 16) gemm_warp<KFT>(WFf, w, a1b + 512, S1, gs, lane);
        __syncthreads();

        {
            float v[4];
#pragma unroll
            for (int j = 0; j < 4; j++) {
                int row = rg*4 + j;
                float hv = gs[n*GSTR + row] + b1n;
                v[j] = w2n * fmaxf(hv, 0.f);
            }
#pragma unroll
            for (int off = 16; off > 0; off >>= 1)
#pragma unroll
                for (int j = 0; j < 4; j++) v[j] += __shfl_down_sync(0xffffffffu, v[j], off);
            if (lane == 0) {
#pragma unroll
                for (int j = 0; j < 4; j++) red[w*4 + j] = v[j];
            }
        }
        __syncthreads();
        if (tid < 16) {
            int row = tid, rgr = row >> 2, jr = row & 3;
            float s = b2v;
#pragma unroll
            for (int ww = 0; ww < 8; ww++) s += red[(rgr*8 + ww)*4 + jr];
            a0s[row*S0 + 32] = __float2half(s);
        }
        __syncthreads();
    }
}

// ---------------- qkv GEMM (R5-verified fp32) ----------------
__global__ void __launch_bounds__(256) qkv_kernel(const float* __restrict__ Winp,
                                                  const float* __restrict__ binp) {
    __shared__ float As[16][128];
    __shared__ float Bs[16][128];
    const int m0 = blockIdx.x * 128;
    const int n0 = blockIdx.y * 128;
    const int tid = threadIdx.x;
    const int tx = tid & 15, ty = tid >> 4;
    float acc[8][8];
#pragma unroll
    for (int i = 0; i < 8; i++)
#pragma unroll
        for (int j = 0; j < 8; j++) acc[i][j] = 0.f;

    for (int k0 = 0; k0 < 256; k0 += 16) {
#pragma unroll
        for (int i = 0; i < 2; i++) {
            int idx = tid + i*256;
            int m = idx >> 2, q = idx & 3;
            float4 a = *(const float4*)&Lg[(size_t)(m0+m)*256 + k0 + q*4];
            As[q*4+0][m]=a.x; As[q*4+1][m]=a.y; As[q*4+2][m]=a.z; As[q*4+3][m]=a.w;
            float4 w = *(const float4*)&Winp[(size_t)(n0+m)*256 + k0 + q*4];
            Bs[q*4+0][m]=w.x; Bs[q*4+1][m]=w.y; Bs[q*4+2][m]=w.z; Bs[q*4+3][m]=w.w;
        }
        __syncthreads();
#pragma unroll
        for (int k = 0; k < 16; k++) {
            float a[8], b[8];
            *(float4*)&a[0] = *(float4*)&As[k][ty*8];
            *(float4*)&a[4] = *(float4*)&As[k][ty*8+4];
            *(float4*)&b[0] = *(float4*)&Bs[k][tx*8];
            *(float4*)&b[4] = *(float4*)&Bs[k][tx*8+4];
#pragma unroll
            for (int i = 0; i < 8; i++)
#pragma unroll
                for (int j = 0; j < 8; j++) acc[i][j] += a[i]*b[j];
        }
        __syncthreads();
    }

    int n_base = n0 + tx*8;
    float bi[8];
#pragma unroll
    for (int j = 0; j < 8; j++) bi[j] = binp[n_base + j];
    int part = n_base >> 8;
    int rem  = n_base & 255;
    int head = rem >> 6;
    int d0   = rem & 63;
#pragma unroll
    for (int i = 0; i < 8; i++) {
        int m = m0 + ty*8 + i;
        int bb = m >> 8, tt = m & 255;
        float* dst = QKVg + ((size_t)((part*BATCH + bb)*4 + head)*TT + tt)*64 + d0;
        float4 o0 = make_float4(acc[i][0]+bi[0], acc[i][1]+bi[1], acc[i][2]+bi[2], acc[i][3]+bi[3]);
        float4 o1 = make_float4(acc[i][4]+bi[4], acc[i][5]+bi[5], acc[i][6]+bi[6], acc[i][7]+bi[7]);
        *(float4*)&dst[0] = o0;
        *(float4*)&dst[4] = o1;
    }
}

// ---------------- attention (R5-verified fp32) ----------------
__global__ void __launch_bounds__(256) attn_kernel() {
    __shared__ float4 Ks[64][16];
    __shared__ float4 Vs[64][16];
    const int b = blockIdx.x, h = blockIdx.y;
    const int t = threadIdx.x;
    const float* Qb = QKVg + ((size_t)(b*4 + h))*TT*64;
    const float* Kb = Qb + PSTR;
    const float* Vb = Kb + PSTR;

    float4 q[16], acc[16];
#pragma unroll
    for (int i = 0; i < 16; i++) {
        q[i] = *(const float4*)&Qb[t*64 + i*4];
        acc[i] = make_float4(0.f, 0.f, 0.f, 0.f);
    }
    float sum = 0.f;

    for (int kc = 0; kc < 4; kc++) {
#pragma unroll
        for (int j = 0; j < 4; j++) {
            int f = t + j*256;
            int row = f >> 4, c = f & 15;
            Ks[row][c] = *(const float4*)&Kb[(size_t)(kc*64 + row)*64 + c*4];
            Vs[row][c] = *(const float4*)&Vb[(size_t)(kc*64 + row)*64 + c*4];
        }
        __syncthreads();
#pragma unroll 2
        for (int k = 0; k < 64; k++) {
            float s = 0.f;
#pragma unroll
            for (int i = 0; i < 16; i++) {
                float4 kv = Ks[k][i];
                s += q[i].x*kv.x + q[i].y*kv.y + q[i].z*kv.z + q[i].w*kv.w;
            }
            float p = __expf(s * 0.125f);
            sum += p;
#pragma unroll
            for (int i = 0; i < 16; i++) {
                float4 vv = Vs[k][i];
                acc[i].x += p*vv.x; acc[i].y += p*vv.y;
                acc[i].z += p*vv.z; acc[i].w += p*vv.w;
            }
        }
        __syncthreads();
    }
    float inv = 1.f / sum;
    float* Cout = CTXg + ((size_t)(b*TT + t))*HH + h*64;
#pragma unroll
    for (int i = 0; i < 16; i++) {
        float4 a = acc[i];
        a.x*=inv; a.y*=inv; a.z*=inv; a.w*=inv;
        *(float4*)&Cout[i*4] = a;
    }
}

// ---------------- final fc (R5-verified fp32) ----------------
__global__ void __launch_bounds__(256) final_kernel(const float* __restrict__ W2,
                                                    const float* __restrict__ b2p,
                                                    float* __restrict__ out) {
    __shared__ float Ls[16][256];
    __shared__ float Cs[16][256];
    __shared__ float red[8][16];
    const int m0 = blockIdx.x * 16;
    const int tid = threadIdx.x;
#pragma unroll
    for (int j = 0; j < 4; j++) {
        int f = tid + j*256;
        int row = f >> 6, c = f & 63;
        *(float4*)&Ls[row][c*4] = *(const float4*)&Lg[(size_t)(m0+row)*256 + c*4];
        *(float4*)&Cs[row][c*4] = *(const float4*)&CTXg[(size_t)(m0+row)*256 + c*4];
    }
    __syncthreads();

    const int r = tid;
    float v[16];
    float bb = b1fw[r];
#pragma unroll
    for (int i = 0; i < 16; i++) v[i] = bb;
#pragma unroll 4
    for (int k = 0; k < 256; k++) {
        float w1 = W1aTw[k*256 + r];
        float wc = WcombTw[k*256 + r];
#pragma unroll
        for (int i = 0; i < 16; i++) v[i] += w1*Ls[i][k] + wc*Cs[i][k];
    }
    float w2 = W2[r];
#pragma unroll
    for (int i = 0; i < 16; i++) v[i] = w2 * fmaxf(v[i], 0.f);
#pragma unroll
    for (int off = 16; off > 0; off >>= 1)
#pragma unroll
        for (int i = 0; i < 16; i++) v[i] += __shfl_down_sync(0xffffffffu, v[i], off);
    int lane = tid & 31, wid = tid >> 5;
    if (lane == 0)
#pragma unroll
        for (int i = 0; i < 16; i++) red[wid][i] = v[i];
    __syncthreads();
    if (tid < 16) {
        float s = b2p[0];
#pragma unroll
        for (int w = 0; w < 8; w++) s += red[w][tid];
        out[m0 + tid] = s;
    }
}

// ---------------- launch ----------------
extern "C" void kernel_launch(void* const* d_in, const int* in_sizes, int n_in,
                              void* d_out, int out_size) {
    (void)in_sizes; (void)n_in; (void)out_size;
    const float* F     = (const float*)d_in[0];
    const float* Wih0  = (const float*)d_in[1];
    const float* Whh0  = (const float*)d_in[2];
    const float* bih0  = (const float*)d_in[3];
    const float* bhh0  = (const float*)d_in[4];
    const float* Wih1  = (const float*)d_in[5];
    const float* Whh1  = (const float*)d_in[6];
    const float* bih1  = (const float*)d_in[7];
    const float* bhh1  = (const float*)d_in[8];
    const float* Winp  = (const float*)d_in[9];
    const float* binp  = (const float*)d_in[10];
    const float* Wop   = (const float*)d_in[11];
    const float* bop   = (const float*)d_in[12];
    const float* W1    = (const float*)d_in[13];
    const float* b1    = (const float*)d_in[14];
    const float* W2    = (const float*)d_in[15];
    const float* b2    = (const float*)d_in[16];
    float* out = (float*)d_out;

    const int SCAN_SMEM = 96768;
    cudaFuncSetAttribute(scan_kernel, cudaFuncAttributeMaxDynamicSharedMemorySize, SCAN_SMEM);

    prep_frag<<<3776, 256>>>(Wih0, Whh0, Wih1, Whh1, W1);
    prep_wcomb<<<256, 256>>>(W1, Wop);
    prep_b1f<<<1, 256>>>(b1, bop, W1);
    scan_kernel<<<NBLK, 1024, SCAN_SMEM>>>(F, bih0, bhh0, bih1, bhh1, b1, W2, b2);
    qkv_kernel<<<dim3(1024, 6), 256>>>(Winp, binp);
    attn_kernel<<<dim3(512, 4), 256>>>();
    final_kernel<<<8192, 256>>>(W2, b2, out);
}

// round 9
// speedup vs baseline: 5.1701x; 1.6964x over previous
#include <cuda_runtime.h>
#include <cuda_fp16.h>
#include <math.h>

#define BATCH 512
#define TT    256
#define DD    32
#define HH    256
#define M_TOTAL (BATCH*TT)
#define PSTR  (BATCH*4*TT*64)

// scan config (clustered)
#define CL   4
#define RPB  16
#define K0T  19      // L0 K tiles: 0-1 x, 2 pd+pad, 3..18 h1
#define K1T  32      // L1 K tiles: 0..15 h1, 16..31 h2
#define KFT  16
#define S0   568     // x(32)|pd(1)|pad(15)|h1b0(256)|h1b1(256)
#define S1   776     // h1(256)|h2b0(256)|h2b1(256)
#define GSTR 17
#define XS   264     // qkv smem row stride (halves)

// ---------------- static device scratch ----------------
__device__ __half W0f[K0T*64*256];
__device__ __half W1f[K1T*64*256];
__device__ __half WFf[KFT*16*256];
__device__ __half WinpH[768*256];     // [n][k] fp16
__device__ float  W1aTw[256*256];
__device__ float  WcombTw[256*256];
__device__ float  b1fw[256];
__device__ float  Lg[M_TOTAL*HH];
__device__ __half Lgh[M_TOTAL*HH];
__device__ float  CTXg[M_TOTAL*HH];
__device__ float  QKVg[3*PSTR];

__device__ __forceinline__ float sigf(float x) { return 1.f / (1.f + __expf(-x)); }
__device__ __forceinline__ float tanh_f(float x) {
    x = fmaxf(fminf(x, 30.f), -30.f);
    float z = __expf(-2.f * x);
    return (1.f - z) / (1.f + z);
}
__device__ __forceinline__ void ldsm4(unsigned &r0, unsigned &r1, unsigned &r2, unsigned &r3, unsigned addr) {
    asm volatile("ldmatrix.sync.aligned.m8n8.x4.shared.b16 {%0,%1,%2,%3}, [%4];"
                 : "=r"(r0),"=r"(r1),"=r"(r2),"=r"(r3) : "r"(addr));
}
__device__ __forceinline__ void ldsm2(unsigned &r0, unsigned &r1, unsigned addr) {
    asm volatile("ldmatrix.sync.aligned.m8n8.x2.shared.b16 {%0,%1}, [%2];"
                 : "=r"(r0),"=r"(r1) : "r"(addr));
}
__device__ __forceinline__ void mma_op(float* c, unsigned a0, unsigned a1, unsigned a2, unsigned a3,
                                       unsigned b0, unsigned b1) {
    asm volatile("mma.sync.aligned.m16n8k16.row.col.f32.f16.f16.f32 "
        "{%0,%1,%2,%3}, {%4,%5,%6,%7}, {%8,%9}, {%0,%1,%2,%3};"
        : "+f"(c[0]), "+f"(c[1]), "+f"(c[2]), "+f"(c[3])
        : "r"(a0), "r"(a1), "r"(a2), "r"(a3), "r"(b0), "r"(b1));
}
__device__ __forceinline__ void cluster_sync_() {
    asm volatile("barrier.cluster.arrive.aligned;\n\tbarrier.cluster.wait.aligned;" ::: "memory");
}
__device__ __forceinline__ void st_cluster_u32(unsigned laddr, unsigned rank, unsigned val) {
    unsigned ra;
    asm volatile("mapa.shared::cluster.u32 %0, %1, %2;" : "=r"(ra) : "r"(laddr), "r"(rank));
    asm volatile("st.shared::cluster.u32 [%0], %1;" :: "r"(ra), "r"(val) : "memory");
}

// ---------------- prep ----------------
__global__ void prep_frag(const float* __restrict__ Wih0, const float* __restrict__ Whh0,
                          const float* __restrict__ Wih1, const float* __restrict__ Whh1,
                          const float* __restrict__ W1,   const float* __restrict__ Winp) {
    int i = blockIdx.x * 256 + threadIdx.x;
    const int E0 = K0T*64*256;          // 311296
    const int E1 = E0 + K1T*64*256;     // 835584
    const int E2 = E1 + KFT*16*256;     // 901120
    const int E3 = E2 + 768*256;        // 1097728
    const int E4 = E3 + 65536;          // 1163264
    if (i < E0) {
        int q = i & 7, lane = (i >> 3) & 31, tile = i >> 8;
        int mt = tile / K0T, kt = tile - mt * K0T;
        int r = lane >> 2, c = lane & 3;
        int dm = r + ((q >> 1) & 1) * 8;
        int dk = 2*c + (q & 1) + ((q >= 4) ? 8 : 0);
        int m = mt*16 + dm, k = kt*16 + dk;
        float v = 0.f;
        if (k < 33) v = Wih0[m*33 + k];
        else if (k >= 48) v = Whh0[m*256 + (k - 48)];
        W0f[i] = __float2half(v);
    } else if (i < E1) {
        int e = i - E0;
        int q = e & 7, lane = (e >> 3) & 31, tile = e >> 8;
        int mt = tile >> 5, kt = tile & 31;
        int r = lane >> 2, c = lane & 3;
        int dm = r + ((q >> 1) & 1) * 8;
        int dk = 2*c + (q & 1) + ((q >= 4) ? 8 : 0);
        int m = mt*16 + dm, k = kt*16 + dk;
        float v = (k < 256) ? Wih1[m*256 + k] : Whh1[m*256 + (k - 256)];
        W1f[e] = __float2half(v);
    } else if (i < E2) {
        int e = i - E1;
        int q = e & 7, lane = (e >> 3) & 31, tile = e >> 8;
        int mt = tile >> 4, kt = tile & 15;
        int r = lane >> 2, c = lane & 3;
        int dm = r + ((q >> 1) & 1) * 8;
        int dk = 2*c + (q & 1) + ((q >= 4) ? 8 : 0);
        int m = mt*16 + dm, k = kt*16 + dk;
        WFf[e] = __float2half(W1[m*512 + k] + W1[m*512 + 256 + k]);
    } else if (i < E3) {
        int e = i - E2;
        WinpH[e] = __float2half(Winp[e]);
    } else if (i < E4) {
        int e = i - E3; int k = e >> 8, r = e & 255;
        W1aTw[e] = W1[r*512 + k];
    }
}

__global__ void prep_wcomb(const float* __restrict__ W1, const float* __restrict__ Wop) {
    int r = blockIdx.x, m = threadIdx.x;
    float s = 0.f;
    for (int k = 0; k < 256; k++) s += W1[r*512 + 256 + k] * Wop[k*256 + m];
    WcombTw[m*256 + r] = s;
}

__global__ void prep_b1f(const float* __restrict__ b1, const float* __restrict__ bop,
                         const float* __restrict__ W1) {
    int r = threadIdx.x;
    float s = b1[r];
    for (int k = 0; k < 256; k++) s += bop[k] * W1[r*512 + 256 + k];
    b1fw[r] = s;
}

// ---------------- scan warp GEMM ----------------
template<int KT, int SPLIT>
__device__ __forceinline__ void gemm_warp(const __half* __restrict__ Wg, int mtA, int mtC,
                                          unsigned actb, int bstr, unsigned extra,
                                          float* __restrict__ gs, int lane) {
    const int r = lane >> 2, c2 = (lane & 3) * 2;
    float acc0[4] = {0.f,0.f,0.f,0.f};
    float acc1[4] = {0.f,0.f,0.f,0.f};
    const uint4* Ap = (const uint4*)Wg + (size_t)mtA*KT*32 + lane;
    const int brow = (lane & 7) + ((lane >> 4) << 3);
    const int bkoff = ((lane >> 3) & 1) * 8;
    const unsigned baddr = actb + (unsigned)((brow*bstr + bkoff) * 2);
#pragma unroll
    for (int kt = 0; kt < KT; kt++) {
        uint4 A = Ap[kt*32];
        unsigned b00, b01, b10, b11;
        unsigned addr = baddr + (unsigned)(kt*32) + ((kt >= SPLIT) ? extra : 0u);
        ldsm4(b00, b01, b10, b11, addr);
        mma_op(acc0, A.x, A.y, A.z, A.w, b00, b01);
        mma_op(acc1, A.x, A.y, A.z, A.w, b10, b11);
    }
    const int m0 = mtC*16;
    float* g0 = gs + (m0 + r)*GSTR + c2;
    float* g1 = gs + (m0 + 8 + r)*GSTR + c2;
    g0[0] = acc0[0]; g0[1] = acc0[1];
    g1[0] = acc0[2]; g1[1] = acc0[3];
    g0[8] = acc1[0]; g0[9] = acc1[1];
    g1[8] = acc1[2]; g1[9] = acc1[3];
}

// ---------------- clustered scan: 128 CTAs (32 clusters x 4), 512 thr ----------------
extern __shared__ char smem_raw[];

__global__ void __launch_bounds__(512, 1) __cluster_dims__(CL, 1, 1)
scan_kernel(const float* __restrict__ F,
            const float* __restrict__ bih0, const float* __restrict__ bhh0,
            const float* __restrict__ bih1, const float* __restrict__ bhh1,
            const float* __restrict__ b1, const float* __restrict__ W2,
            const float* __restrict__ b2p)
{
    float*  gs  = (float*)smem_raw;                 // 256*17*4 = 17408
    __half* a0s = (__half*)(smem_raw + 17408);      // 16*568*2 = 18176
    __half* a1s = (__half*)(smem_raw + 35584);      // 16*776*2 = 24832 -> 60416

    const int tid = threadIdx.x;
    const int w = tid >> 5, lane = tid & 31;
    unsigned crank; asm("mov.u32 %0, %%cluster_ctarank;" : "=r"(crank));
    const int b0r = (blockIdx.x >> 2) * RPB;
    const int nbase = (int)crank * 64;
    const int ar = w;                  // batch row 0..15
    const int u  = lane * 2;           // local neuron (even)
    const int ng = nbase + u;          // global neuron

    const unsigned a0b = (unsigned)__cvta_generic_to_shared(a0s);
    const unsigned a1b = (unsigned)__cvta_generic_to_shared(a1s);

    const int gq = w >> 2, qq = w & 3;
    const int mtA01 = gq*16 + (int)crank*4 + qq;   // m-tile in W0f/W1f for this warp

    float bi0[2][4], bi1[2][4];
#pragma unroll
    for (int j = 0; j < 2; j++)
#pragma unroll
        for (int g = 0; g < 4; g++) {
            bi0[j][g] = bih0[g*256 + ng + j] + bhh0[g*256 + ng + j];
            bi1[j][g] = bih1[g*256 + ng + j] + bhh1[g*256 + ng + j];
        }
    float w2v[8], b1v[8];
#pragma unroll
    for (int i = 0; i < 8; i++) { w2v[i] = W2[lane + 32*i]; b1v[i] = b1[lane + 32*i]; }
    const float b2v = b2p[0];
    float c1v[2] = {0.f, 0.f}, c2v[2] = {0.f, 0.f};

    const __half hz = __float2half(0.f);
    for (int i = tid; i < 16*S0; i += 512) a0s[i] = hz;
    for (int i = tid; i < 16*S1; i += 512) a1s[i] = hz;
    cluster_sync_();

    for (int t = 0; t < TT; t++) {
        const int hb = t & 1;                           // write buffer
        const unsigned pext = (unsigned)(((t + 1) & 1) * 512);  // read-buffer byte offset

        // stage x (one element per thread: 16 rows x 32)
        a0s[ar*S0 + lane] = __float2half(F[(size_t)(b0r + ar)*(TT*DD) + t*DD + lane]);
        __syncthreads();

        // L0 gates: this CTA's 256 gate-lines
        gemm_warp<K0T, 3>(W0f, mtA01, w, a0b, S0, pext, gs, lane);
        __syncthreads();

        // L0 activation (thread: row ar, neurons u,u+1)
        {
            float h1p[2];
#pragma unroll
            for (int j = 0; j < 2; j++) {
                float gi = gs[(      u + j)*GSTR + ar] + bi0[j][0];
                float gf = gs[( 64 + u + j)*GSTR + ar] + bi0[j][1];
                float gG = gs[(128 + u + j)*GSTR + ar] + bi0[j][2];
                float go = gs[(192 + u + j)*GSTR + ar] + bi0[j][3];
                c1v[j] = sigf(gf)*c1v[j] + sigf(gi)*tanh_f(gG);
                h1p[j] = sigf(go)*tanh_f(c1v[j]);
            }
            __half2 hp = __floats2half2_rn(h1p[0], h1p[1]);
            unsigned hv = *(unsigned*)&hp;
            unsigned o0 = a0b + (unsigned)((ar*S0 + 48 + hb*256 + ng) * 2);
            unsigned o1 = a1b + (unsigned)((ar*S1 + ng) * 2);
#pragma unroll
            for (unsigned rk = 0; rk < CL; rk++) {
                st_cluster_u32(o0, rk, hv);
                st_cluster_u32(o1, rk, hv);
            }
        }
        cluster_sync_();   // h1(t) visible everywhere

        // L1 gates
        gemm_warp<K1T, 16>(W1f, mtA01, w, a1b, S1, pext, gs, lane);
        __syncthreads();

        // L1 activation
        {
            float h2p[2];
#pragma unroll
            for (int j = 0; j < 2; j++) {
                float gi = gs[(      u + j)*GSTR + ar] + bi1[j][0];
                float gf = gs[( 64 + u + j)*GSTR + ar] + bi1[j][1];
                float gG = gs[(128 + u + j)*GSTR + ar] + bi1[j][2];
                float go = gs[(192 + u + j)*GSTR + ar] + bi1[j][3];
                c2v[j] = sigf(gf)*c2v[j] + sigf(gi)*tanh_f(gG);
                h2p[j] = sigf(go)*tanh_f(c2v[j]);
            }
            __half2 hp = __floats2half2_rn(h2p[0], h2p[1]);
            unsigned hv = *(unsigned*)&hp;
            unsigned o2 = a1b + (unsigned)((ar*S1 + 256 + hb*256 + ng) * 2);
#pragma unroll
            for (unsigned rk = 0; rk < CL; rk++) st_cluster_u32(o2, rk, hv);
            size_t gidx = (size_t)(b0r + ar)*(TT*HH) + (size_t)t*HH + ng;
            *(float2*)&Lg[gidx] = make_float2(h2p[0], h2p[1]);
            *(__half2*)&Lgh[gidx] = hp;
        }
        cluster_sync_();   // h2(t) visible everywhere

        // fc hidden: full 256 units per CTA (redundant, avoids pd exchange)
        gemm_warp<KFT, 99>(WFf, w, w, a1b + 512u + (unsigned)(hb*512), S1, 0u, gs, lane);
        __syncthreads();

        // pd reduce (warp ar covers all 256 hidden units)
        {
            float v = 0.f;
#pragma unroll
            for (int i = 0; i < 8; i++)
                v += w2v[i] * fmaxf(gs[(lane + 32*i)*GSTR + ar] + b1v[i], 0.f);
#pragma unroll
            for (int off = 16; off > 0; off >>= 1)
                v += __shfl_down_sync(0xffffffffu, v, off);
            if (lane == 0) a0s[ar*S0 + 32] = __float2half(v + b2v);
        }
        // next-iteration top __syncthreads orders pd/gs hazards
    }
}

// ---------------- qkv HMMA GEMM: [131072 x 768] = Lgh @ WinpH^T ----------------
__global__ void __launch_bounds__(256) qkv_hmma(const float* __restrict__ binp) {
    extern __shared__ char sm[];
    __half* Xs  = (__half*)sm;                   // 128*264
    __half* Wsh = (__half*)(sm + 128*XS*2);      // 64*264
    const int m0 = blockIdx.x * 128;
    const int n0 = blockIdx.y * 64;
    const int tid = threadIdx.x, w = tid >> 5, lane = tid & 31;

    {
        const uint4* src = (const uint4*)(Lgh + (size_t)m0*256);
#pragma unroll
        for (int i = 0; i < 16; i++) {
            int idx = tid + i*256;
            int row = idx >> 5, q = idx & 31;
            *(uint4*)(Xs + row*XS + q*8) = src[row*32 + q];
        }
        const uint4* wsrc = (const uint4*)(WinpH + (size_t)n0*256);
#pragma unroll
        for (int i = 0; i < 8; i++) {                    // FIX: was 4 — staged only half of Wsh
            int idx = tid + i*256;                       // 0..2047 uint4 = 64 rows x 32
            int row = idx >> 5, q = idx & 31;
            *(uint4*)(Wsh + row*XS + q*8) = wsrc[row*32 + q];
        }
    }
    __syncthreads();

    float acc[8][4];
#pragma unroll
    for (int i = 0; i < 8; i++)
#pragma unroll
        for (int j = 0; j < 4; j++) acc[i][j] = 0.f;

    const int arow = (lane & 7) + (((lane >> 3) & 1) << 3);
    const int akoff = ((lane >> 4) & 1) * 8;
    const unsigned abase = (unsigned)__cvta_generic_to_shared(Xs)
                         + (unsigned)(((w*16 + arow)*XS + akoff)*2);
    const unsigned bbase = (unsigned)__cvta_generic_to_shared(Wsh)
                         + (unsigned)((((lane & 7)*XS) + ((lane >> 3) & 1)*8)*2);

#pragma unroll
    for (int kt = 0; kt < 16; kt++) {
        unsigned a0,a1,a2,a3;
        ldsm4(a0,a1,a2,a3, abase + kt*32);
#pragma unroll
        for (int nt = 0; nt < 8; nt++) {
            unsigned b0,b1;
            ldsm2(b0,b1, bbase + (unsigned)(nt*8*XS*2) + kt*32);
            mma_op(acc[nt], a0,a1,a2,a3, b0,b1);
        }
    }

    const int r = lane >> 2, c = lane & 3;
    const int m1 = m0 + w*16 + r, m2 = m1 + 8;
    const int bb1 = m1 >> 8, tt1 = m1 & 255;
    const int bb2 = m2 >> 8, tt2 = m2 & 255;
#pragma unroll
    for (int nt = 0; nt < 8; nt++) {
        int nn = n0 + nt*8 + 2*c;
        float bi0 = binp[nn], bi1 = binp[nn+1];
        int part = nn >> 8, head = (nn >> 6) & 3, d = nn & 63;
        float* d1 = QKVg + ((size_t)((part*BATCH + bb1)*4 + head)*TT + tt1)*64 + d;
        float* d2 = QKVg + ((size_t)((part*BATCH + bb2)*4 + head)*TT + tt2)*64 + d;
        float2 v1; v1.x = acc[nt][0]+bi0; v1.y = acc[nt][1]+bi1;
        float2 v2; v2.x = acc[nt][2]+bi0; v2.y = acc[nt][3]+bi1;
        *(float2*)d1 = v1;
        *(float2*)d2 = v2;
    }
}

// ---------------- attention (fp32, R7-verified) ----------------
__global__ void __launch_bounds__(256) attn_kernel() {
    __shared__ float4 Ks[64][16];
    __shared__ float4 Vs[64][16];
    const int b = blockIdx.x, h = blockIdx.y;
    const int t = threadIdx.x;
    const float* Qb = QKVg + ((size_t)(b*4 + h))*TT*64;
    const float* Kb = Qb + PSTR;
    const float* Vb = Kb + PSTR;

    float4 q[16], acc[16];
#pragma unroll
    for (int i = 0; i < 16; i++) {
        q[i] = *(const float4*)&Qb[t*64 + i*4];
        acc[i] = make_float4(0.f, 0.f, 0.f, 0.f);
    }
    float sum = 0.f;

    for (int kc = 0; kc < 4; kc++) {
#pragma unroll
        for (int j = 0; j < 4; j++) {
            int f = t + j*256;
            int row = f >> 4, c = f & 15;
            Ks[row][c] = *(const float4*)&Kb[(size_t)(kc*64 + row)*64 + c*4];
            Vs[row][c] = *(const float4*)&Vb[(size_t)(kc*64 + row)*64 + c*4];
        }
        __syncthreads();
#pragma unroll 2
        for (int k = 0; k < 64; k++) {
            float s = 0.f;
#pragma unroll
            for (int i = 0; i < 16; i++) {
                float4 kv = Ks[k][i];
                s += q[i].x*kv.x + q[i].y*kv.y + q[i].z*kv.z + q[i].w*kv.w;
            }
            float p = __expf(s * 0.125f);
            sum += p;
#pragma unroll
            for (int i = 0; i < 16; i++) {
                float4 vv = Vs[k][i];
                acc[i].x += p*vv.x; acc[i].y += p*vv.y;
                acc[i].z += p*vv.z; acc[i].w += p*vv.w;
            }
        }
        __syncthreads();
    }
    float inv = 1.f / sum;
    float* Cout = CTXg + ((size_t)(b*TT + t))*HH + h*64;
#pragma unroll
    for (int i = 0; i < 16; i++) {
        float4 a = acc[i];
        a.x*=inv; a.y*=inv; a.z*=inv; a.w*=inv;
        *(float4*)&Cout[i*4] = a;
    }
}

// ---------------- final fc (fp32, R7-verified) ----------------
__global__ void __launch_bounds__(256) final_kernel(const float* __restrict__ W2,
                                                    const float* __restrict__ b2p,
                                                    float* __restrict__ out) {
    __shared__ float Ls[16][256];
    __shared__ float Cs[16][256];
    __shared__ float red[8][16];
    const int m0 = blockIdx.x * 16;
    const int tid = threadIdx.x;
#pragma unroll
    for (int j = 0; j < 4; j++) {
        int f = tid + j*256;
        int row = f >> 6, c = f & 63;
        *(float4*)&Ls[row][c*4] = *(const float4*)&Lg[(size_t)(m0+row)*256 + c*4];
        *(float4*)&Cs[row][c*4] = *(const float4*)&CTXg[(size_t)(m0+row)*256 + c*4];
    }
    __syncthreads();

    const int r = tid;
    float v[16];
    float bb = b1fw[r];
#pragma unroll
    for (int i = 0; i < 16; i++) v[i] = bb;
#pragma unroll 4
    for (int k = 0; k < 256; k++) {
        float w1 = W1aTw[k*256 + r];
        float wc = WcombTw[k*256 + r];
#pragma unroll
        for (int i = 0; i < 16; i++) v[i] += w1*Ls[i][k] + wc*Cs[i][k];
    }
    float w2 = W2[r];
#pragma unroll
    for (int i = 0; i < 16; i++) v[i] = w2 * fmaxf(v[i], 0.f);
#pragma unroll
    for (int off = 16; off > 0; off >>= 1)
#pragma unroll
        for (int i = 0; i < 16; i++) v[i] += __shfl_down_sync(0xffffffffu, v[i], off);
    int lane = tid & 31, wid = tid >> 5;
    if (lane == 0)
#pragma unroll
        for (int i = 0; i < 16; i++) red[wid][i] = v[i];
    __syncthreads();
    if (tid < 16) {
        float s = b2p[0];
#pragma unroll
        for (int w = 0; w < 8; w++) s += red[w][tid];
        out[m0 + tid] = s;
    }
}

// ---------------- launch ----------------
extern "C" void kernel_launch(void* const* d_in, const int* in_sizes, int n_in,
                              void* d_out, int out_size) {
    (void)in_sizes; (void)n_in; (void)out_size;
    const float* F     = (const float*)d_in[0];
    const float* Wih0  = (const float*)d_in[1];
    const float* Whh0  = (const float*)d_in[2];
    const float* bih0  = (const float*)d_in[3];
    const float* bhh0  = (const float*)d_in[4];
    const float* Wih1  = (const float*)d_in[5];
    const float* Whh1  = (const float*)d_in[6];
    const float* bih1  = (const float*)d_in[7];
    const float* bhh1  = (const float*)d_in[8];
    const float* Winp  = (const float*)d_in[9];
    const float* binp  = (const float*)d_in[10];
    const float* Wop   = (const float*)d_in[11];
    const float* bop   = (const float*)d_in[12];
    const float* W1    = (const float*)d_in[13];
    const float* b1    = (const float*)d_in[14];
    const float* W2    = (const float*)d_in[15];
    const float* b2    = (const float*)d_in[16];
    float* out = (float*)d_out;

    const int SCAN_SMEM = 60416;
    const int QKV_SMEM  = (128*XS + 64*XS)*2;
    cudaFuncSetAttribute(scan_kernel, cudaFuncAttributeMaxDynamicSharedMemorySize, SCAN_SMEM);
    cudaFuncSetAttribute(qkv_hmma,    cudaFuncAttributeMaxDynamicSharedMemorySize, QKV_SMEM);

    prep_frag<<<4544, 256>>>(Wih0, Whh0, Wih1, Whh1, W1, Winp);
    prep_wcomb<<<256, 256>>>(W1, Wop);
    prep_b1f<<<1, 256>>>(b1, bop, W1);
    scan_kernel<<<128, 512, SCAN_SMEM>>>(F, bih0, bhh0, bih1, bhh1, b1, W2, b2);
    qkv_hmma<<<dim3(1024, 12), 256, QKV_SMEM>>>(binp);
    attn_kernel<<<dim3(512, 4), 256>>>();
    final_kernel<<<8192, 256>>>(W2, b2, out);
}

// round 11
// speedup vs baseline: 9.4814x; 1.8339x over previous
#include <cuda_runtime.h>
#include <cuda_fp16.h>
#include <math.h>

#define BATCH 512
#define TT    256
#define DD    32
#define HH    256
#define M_TOTAL (BATCH*TT)
#define PSTR  (BATCH*4*TT*64)

// scan config (clustered)
#define CL   4
#define RPB  16
#define K0T  19
#define K1T  32
#define KFT  16
#define S0   568
#define S1   776
#define GSTR 17
#define XS   264     // qkv smem row stride (halves)
#define QS   72      // attn smem row stride (halves)
#define FS   136     // final smem row stride (halves)

// ---------------- static device scratch ----------------
__device__ __half W0f[K0T*64*256];
__device__ __half W1f[K1T*64*256];
__device__ __half WFf[KFT*16*256];
__device__ __half WinpH[768*256];     // [n][k] fp16
__device__ __half WfinH[256*512];     // [r][k]: k<256 W1a, k>=256 Wcomb
__device__ float  b1fw[256];
__device__ __half Lgh[M_TOTAL*HH];
__device__ __half CTXh[M_TOTAL*HH];
__device__ float  QKVg[3*PSTR];

__device__ __forceinline__ float sigf(float x) { return 1.f / (1.f + __expf(-x)); }
__device__ __forceinline__ float tanh_f(float x) {
    x = fmaxf(fminf(x, 30.f), -30.f);
    float z = __expf(-2.f * x);
    return (1.f - z) / (1.f + z);
}
__device__ __forceinline__ void ldsm4(unsigned &r0, unsigned &r1, unsigned &r2, unsigned &r3, unsigned addr) {
    asm volatile("ldmatrix.sync.aligned.m8n8.x4.shared.b16 {%0,%1,%2,%3}, [%4];"
                 : "=r"(r0),"=r"(r1),"=r"(r2),"=r"(r3) : "r"(addr));
}
__device__ __forceinline__ void ldsm2(unsigned &r0, unsigned &r1, unsigned addr) {
    asm volatile("ldmatrix.sync.aligned.m8n8.x2.shared.b16 {%0,%1}, [%2];"
                 : "=r"(r0),"=r"(r1) : "r"(addr));
}
__device__ __forceinline__ void mma_op(float* c, unsigned a0, unsigned a1, unsigned a2, unsigned a3,
                                       unsigned b0, unsigned b1) {
    asm volatile("mma.sync.aligned.m16n8k16.row.col.f32.f16.f16.f32 "
        "{%0,%1,%2,%3}, {%4,%5,%6,%7}, {%8,%9}, {%0,%1,%2,%3};"
        : "+f"(c[0]), "+f"(c[1]), "+f"(c[2]), "+f"(c[3])
        : "r"(a0), "r"(a1), "r"(a2), "r"(a3), "r"(b0), "r"(b1));
}
__device__ __forceinline__ unsigned pack_h2(float a, float b) {
    __half2 h = __floats2half2_rn(a, b);
    return *(unsigned*)&h;
}
__device__ __forceinline__ void cluster_sync_() {
    asm volatile("barrier.cluster.arrive.aligned;\n\tbarrier.cluster.wait.aligned;" ::: "memory");
}
__device__ __forceinline__ void st_cluster_u32(unsigned laddr, unsigned rank, unsigned val) {
    unsigned ra;
    asm volatile("mapa.shared::cluster.u32 %0, %1, %2;" : "=r"(ra) : "r"(laddr), "r"(rank));
    asm volatile("st.shared::cluster.u32 [%0], %1;" :: "r"(ra), "r"(val) : "memory");
}

// ---------------- prep ----------------
__global__ void prep_frag(const float* __restrict__ Wih0, const float* __restrict__ Whh0,
                          const float* __restrict__ Wih1, const float* __restrict__ Whh1,
                          const float* __restrict__ W1,   const float* __restrict__ Winp) {
    int i = blockIdx.x * 256 + threadIdx.x;
    const int E0 = K0T*64*256;          // 311296
    const int E1 = E0 + K1T*64*256;     // 835584
    const int E2 = E1 + KFT*16*256;     // 901120
    const int E3 = E2 + 768*256;        // 1097728
    const int E4 = E3 + 65536;          // 1163264
    if (i < E0) {
        int q = i & 7, lane = (i >> 3) & 31, tile = i >> 8;
        int mt = tile / K0T, kt = tile - mt * K0T;
        int r = lane >> 2, c = lane & 3;
        int dm = r + ((q >> 1) & 1) * 8;
        int dk = 2*c + (q & 1) + ((q >= 4) ? 8 : 0);
        int m = mt*16 + dm, k = kt*16 + dk;
        float v = 0.f;
        if (k < 33) v = Wih0[m*33 + k];
        else if (k >= 48) v = Whh0[m*256 + (k - 48)];
        W0f[i] = __float2half(v);
    } else if (i < E1) {
        int e = i - E0;
        int q = e & 7, lane = (e >> 3) & 31, tile = e >> 8;
        int mt = tile >> 5, kt = tile & 31;
        int r = lane >> 2, c = lane & 3;
        int dm = r + ((q >> 1) & 1) * 8;
        int dk = 2*c + (q & 1) + ((q >= 4) ? 8 : 0);
        int m = mt*16 + dm, k = kt*16 + dk;
        float v = (k < 256) ? Wih1[m*256 + k] : Whh1[m*256 + (k - 256)];
        W1f[e] = __float2half(v);
    } else if (i < E2) {
        int e = i - E1;
        int q = e & 7, lane = (e >> 3) & 31, tile = e >> 8;
        int mt = tile >> 4, kt = tile & 15;
        int r = lane >> 2, c = lane & 3;
        int dm = r + ((q >> 1) & 1) * 8;
        int dk = 2*c + (q & 1) + ((q >= 4) ? 8 : 0);
        int m = mt*16 + dm, k = kt*16 + dk;
        WFf[e] = __float2half(W1[m*512 + k] + W1[m*512 + 256 + k]);
    } else if (i < E3) {
        int e = i - E2;
        WinpH[e] = __float2half(Winp[e]);
    } else if (i < E4) {
        int e = i - E3; int r = e >> 8, k = e & 255;
        WfinH[r*512 + k] = __float2half(W1[r*512 + k]);
    }
}

__global__ void prep_wcomb(const float* __restrict__ W1, const float* __restrict__ Wop) {
    int r = blockIdx.x, m = threadIdx.x;
    float s = 0.f;
    for (int k = 0; k < 256; k++) s += W1[r*512 + 256 + k] * Wop[k*256 + m];
    WfinH[r*512 + 256 + m] = __float2half(s);
}

__global__ void prep_b1f(const float* __restrict__ b1, const float* __restrict__ bop,
                         const float* __restrict__ W1) {
    int r = threadIdx.x;
    float s = b1[r];
    for (int k = 0; k < 256; k++) s += bop[k] * W1[r*512 + 256 + k];
    b1fw[r] = s;
}

// ---------------- scan warp GEMM ----------------
template<int KT, int SPLIT>
__device__ __forceinline__ void gemm_warp(const __half* __restrict__ Wg, int mtA, int mtC,
                                          unsigned actb, int bstr, unsigned extra,
                                          float* __restrict__ gs, int lane) {
    const int r = lane >> 2, c2 = (lane & 3) * 2;
    float acc0[4] = {0.f,0.f,0.f,0.f};
    float acc1[4] = {0.f,0.f,0.f,0.f};
    const uint4* Ap = (const uint4*)Wg + (size_t)mtA*KT*32 + lane;
    const int brow = (lane & 7) + ((lane >> 4) << 3);
    const int bkoff = ((lane >> 3) & 1) * 8;
    const unsigned baddr = actb + (unsigned)((brow*bstr + bkoff) * 2);
#pragma unroll
    for (int kt = 0; kt < KT; kt++) {
        uint4 A = Ap[kt*32];
        unsigned b00, b01, b10, b11;
        unsigned addr = baddr + (unsigned)(kt*32) + ((kt >= SPLIT) ? extra : 0u);
        ldsm4(b00, b01, b10, b11, addr);
        mma_op(acc0, A.x, A.y, A.z, A.w, b00, b01);
        mma_op(acc1, A.x, A.y, A.z, A.w, b10, b11);
    }
    const int m0 = mtC*16;
    float* g0 = gs + (m0 + r)*GSTR + c2;
    float* g1 = gs + (m0 + 8 + r)*GSTR + c2;
    g0[0] = acc0[0]; g0[1] = acc0[1];
    g1[0] = acc0[2]; g1[1] = acc0[3];
    g0[8] = acc1[0]; g0[9] = acc1[1];
    g1[8] = acc1[2]; g1[9] = acc1[3];
}

// ---------------- clustered scan ----------------
extern __shared__ char smem_raw[];

__global__ void __launch_bounds__(512, 1) __cluster_dims__(CL, 1, 1)
scan_kernel(const float* __restrict__ F,
            const float* __restrict__ bih0, const float* __restrict__ bhh0,
            const float* __restrict__ bih1, const float* __restrict__ bhh1,
            const float* __restrict__ b1, const float* __restrict__ W2,
            const float* __restrict__ b2p)
{
    float*  gs  = (float*)smem_raw;
    __half* a0s = (__half*)(smem_raw + 17408);
    __half* a1s = (__half*)(smem_raw + 35584);

    const int tid = threadIdx.x;
    const int w = tid >> 5, lane = tid & 31;
    unsigned crank; asm("mov.u32 %0, %%cluster_ctarank;" : "=r"(crank));
    const int b0r = (blockIdx.x >> 2) * RPB;
    const int nbase = (int)crank * 64;
    const int ar = w;
    const int u  = lane * 2;
    const int ng = nbase + u;

    const unsigned a0b = (unsigned)__cvta_generic_to_shared(a0s);
    const unsigned a1b = (unsigned)__cvta_generic_to_shared(a1s);

    const int gq = w >> 2, qq = w & 3;
    const int mtA01 = gq*16 + (int)crank*4 + qq;

    float bi0[2][4], bi1[2][4];
#pragma unroll
    for (int j = 0; j < 2; j++)
#pragma unroll
        for (int g = 0; g < 4; g++) {
            bi0[j][g] = bih0[g*256 + ng + j] + bhh0[g*256 + ng + j];
            bi1[j][g] = bih1[g*256 + ng + j] + bhh1[g*256 + ng + j];
        }
    float w2v[8], b1v[8];
#pragma unroll
    for (int i = 0; i < 8; i++) { w2v[i] = W2[lane + 32*i]; b1v[i] = b1[lane + 32*i]; }
    const float b2v = b2p[0];
    float c1v[2] = {0.f, 0.f}, c2v[2] = {0.f, 0.f};

    const __half hz = __float2half(0.f);
    for (int i = tid; i < 16*S0; i += 512) a0s[i] = hz;
    for (int i = tid; i < 16*S1; i += 512) a1s[i] = hz;
    cluster_sync_();

    for (int t = 0; t < TT; t++) {
        const int hb = t & 1;
        const unsigned pext = (unsigned)(((t + 1) & 1) * 512);

        a0s[ar*S0 + lane] = __float2half(F[(size_t)(b0r + ar)*(TT*DD) + t*DD + lane]);
        __syncthreads();

        gemm_warp<K0T, 3>(W0f, mtA01, w, a0b, S0, pext, gs, lane);
        __syncthreads();

        {
            float h1p[2];
#pragma unroll
            for (int j = 0; j < 2; j++) {
                float gi = gs[(      u + j)*GSTR + ar] + bi0[j][0];
                float gf = gs[( 64 + u + j)*GSTR + ar] + bi0[j][1];
                float gG = gs[(128 + u + j)*GSTR + ar] + bi0[j][2];
                float go = gs[(192 + u + j)*GSTR + ar] + bi0[j][3];
                c1v[j] = sigf(gf)*c1v[j] + sigf(gi)*tanh_f(gG);
                h1p[j] = sigf(go)*tanh_f(c1v[j]);
            }
            unsigned hv = pack_h2(h1p[0], h1p[1]);
            unsigned o0 = a0b + (unsigned)((ar*S0 + 48 + hb*256 + ng) * 2);
            unsigned o1 = a1b + (unsigned)((ar*S1 + ng) * 2);
#pragma unroll
            for (unsigned rk = 0; rk < CL; rk++) {
                st_cluster_u32(o0, rk, hv);
                st_cluster_u32(o1, rk, hv);
            }
        }
        cluster_sync_();

        gemm_warp<K1T, 16>(W1f, mtA01, w, a1b, S1, pext, gs, lane);
        __syncthreads();

        {
            float h2p[2];
#pragma unroll
            for (int j = 0; j < 2; j++) {
                float gi = gs[(      u + j)*GSTR + ar] + bi1[j][0];
                float gf = gs[( 64 + u + j)*GSTR + ar] + bi1[j][1];
                float gG = gs[(128 + u + j)*GSTR + ar] + bi1[j][2];
                float go = gs[(192 + u + j)*GSTR + ar] + bi1[j][3];
                c2v[j] = sigf(gf)*c2v[j] + sigf(gi)*tanh_f(gG);
                h2p[j] = sigf(go)*tanh_f(c2v[j]);
            }
            unsigned hv = pack_h2(h2p[0], h2p[1]);
            unsigned o2 = a1b + (unsigned)((ar*S1 + 256 + hb*256 + ng) * 2);
#pragma unroll
            for (unsigned rk = 0; rk < CL; rk++) st_cluster_u32(o2, rk, hv);
            size_t gidx = (size_t)(b0r + ar)*(TT*HH) + (size_t)t*HH + ng;
            *(unsigned*)&Lgh[gidx] = hv;
        }
        cluster_sync_();

        gemm_warp<KFT, 99>(WFf, w, w, a1b + 512u + (unsigned)(hb*512), S1, 0u, gs, lane);
        __syncthreads();

        {
            float v = 0.f;
#pragma unroll
            for (int i = 0; i < 8; i++)
                v += w2v[i] * fmaxf(gs[(lane + 32*i)*GSTR + ar] + b1v[i], 0.f);
#pragma unroll
            for (int off = 16; off > 0; off >>= 1)
                v += __shfl_down_sync(0xffffffffu, v, off);
            if (lane == 0) a0s[ar*S0 + 32] = __float2half(v + b2v);
        }
    }
}

// ---------------- qkv HMMA GEMM (R9-verified) ----------------
__global__ void __launch_bounds__(256) qkv_hmma(const float* __restrict__ binp) {
    extern __shared__ char sm[];
    __half* Xs  = (__half*)sm;
    __half* Wsh = (__half*)(sm + 128*XS*2);
    const int m0 = blockIdx.x * 128;
    const int n0 = blockIdx.y * 64;
    const int tid = threadIdx.x, w = tid >> 5, lane = tid & 31;

    {
        const uint4* src = (const uint4*)(Lgh + (size_t)m0*256);
#pragma unroll
        for (int i = 0; i < 16; i++) {
            int idx = tid + i*256;
            int row = idx >> 5, q = idx & 31;
            *(uint4*)(Xs + row*XS + q*8) = src[row*32 + q];
        }
        const uint4* wsrc = (const uint4*)(WinpH + (size_t)n0*256);
#pragma unroll
        for (int i = 0; i < 8; i++) {
            int idx = tid + i*256;
            int row = idx >> 5, q = idx & 31;
            *(uint4*)(Wsh + row*XS + q*8) = wsrc[row*32 + q];
        }
    }
    __syncthreads();

    float acc[8][4];
#pragma unroll
    for (int i = 0; i < 8; i++)
#pragma unroll
        for (int j = 0; j < 4; j++) acc[i][j] = 0.f;

    const int arow = (lane & 7) + (((lane >> 3) & 1) << 3);
    const int akoff = ((lane >> 4) & 1) * 8;
    const unsigned abase = (unsigned)__cvta_generic_to_shared(Xs)
                         + (unsigned)(((w*16 + arow)*XS + akoff)*2);
    const unsigned bbase = (unsigned)__cvta_generic_to_shared(Wsh)
                         + (unsigned)((((lane & 7)*XS) + ((lane >> 3) & 1)*8)*2);

#pragma unroll
    for (int kt = 0; kt < 16; kt++) {
        unsigned a0,a1,a2,a3;
        ldsm4(a0,a1,a2,a3, abase + kt*32);
#pragma unroll
        for (int nt = 0; nt < 8; nt++) {
            unsigned b0,b1;
            ldsm2(b0,b1, bbase + (unsigned)(nt*8*XS*2) + kt*32);
            mma_op(acc[nt], a0,a1,a2,a3, b0,b1);
        }
    }

    const int r = lane >> 2, c = lane & 3;
    const int m1 = m0 + w*16 + r, m2 = m1 + 8;
    const int bb1 = m1 >> 8, tt1 = m1 & 255;
    const int bb2 = m2 >> 8, tt2 = m2 & 255;
#pragma unroll
    for (int nt = 0; nt < 8; nt++) {
        int nn = n0 + nt*8 + 2*c;
        float bi0 = binp[nn], bi1 = binp[nn+1];
        int part = nn >> 8, head = (nn >> 6) & 3, d = nn & 63;
        float* d1 = QKVg + ((size_t)((part*BATCH + bb1)*4 + head)*TT + tt1)*64 + d;
        float* d2 = QKVg + ((size_t)((part*BATCH + bb2)*4 + head)*TT + tt2)*64 + d;
        float2 v1; v1.x = acc[nt][0]+bi0; v1.y = acc[nt][1]+bi1;
        float2 v2; v2.x = acc[nt][2]+bi0; v2.y = acc[nt][3]+bi1;
        *(float2*)d1 = v1;
        *(float2*)d2 = v2;
    }
}

// ---------------- attention HMMA: block=(b,h), 8 warps x 32 query rows ----------------
__global__ void __launch_bounds__(256, 1) attn_hmma() {
    extern __shared__ char sm[];
    __half* Qs = (__half*)sm;                       // 256*72 = 36864 B
    __half* Ks = (__half*)(sm + 36864);             // 64*72  =  9216 B
    __half* Vt = (__half*)(sm + 46080);             // 64*72  =  9216 B  (Vt[d][key])
    const int b = blockIdx.x, h = blockIdx.y;
    const int tid = threadIdx.x, w = tid >> 5, lane = tid & 31;
    const float* Qb = QKVg + ((size_t)(b*4 + h))*TT*64;
    const float* Kb = Qb + PSTR;
    const float* Vb = Kb + PSTR;

    // stage Q fp32->fp16 (256 rows x 64)
#pragma unroll
    for (int i = 0; i < 16; i++) {
        int idx = tid + i*256;
        int row = idx >> 4, d4 = idx & 15;
        float4 v = *(const float4*)&Qb[(size_t)row*64 + d4*4];
        unsigned u01 = pack_h2(v.x, v.y), u23 = pack_h2(v.z, v.w);
        *(unsigned*)&Qs[row*QS + d4*4]     = u01;
        *(unsigned*)&Qs[row*QS + d4*4 + 2] = u23;
    }
    __syncthreads();

    // preload Q A-fragments: 2 m-tiles x 4 k-tiles
    const int arow = (lane & 7) + (((lane >> 3) & 1) << 3);
    const int akoff = ((lane >> 4) & 1) * 8;
    unsigned aQ[2][4][4];
#pragma unroll
    for (int mt = 0; mt < 2; mt++) {
        unsigned abase = (unsigned)__cvta_generic_to_shared(Qs)
                       + (unsigned)(((w*32 + mt*16 + arow)*QS + akoff)*2);
#pragma unroll
        for (int kt = 0; kt < 4; kt++)
            ldsm4(aQ[mt][kt][0], aQ[mt][kt][1], aQ[mt][kt][2], aQ[mt][kt][3], abase + kt*32);
    }

    const unsigned bK = (unsigned)__cvta_generic_to_shared(Ks)
                      + (unsigned)((((lane & 7)*QS) + ((lane >> 3) & 1)*8)*2);
    const unsigned bV = (unsigned)__cvta_generic_to_shared(Vt)
                      + (unsigned)((((lane & 7)*QS) + ((lane >> 3) & 1)*8)*2);

    float oacc[2][8][4];
#pragma unroll
    for (int mt = 0; mt < 2; mt++)
#pragma unroll
        for (int nt = 0; nt < 8; nt++)
#pragma unroll
            for (int i = 0; i < 4; i++) oacc[mt][nt][i] = 0.f;
    float rs[2][2] = {{0.f,0.f},{0.f,0.f}};

    for (int kc = 0; kc < 4; kc++) {
        // stage K chunk (64 x 64)
#pragma unroll
        for (int i = 0; i < 4; i++) {
            int idx = tid + i*256;
            int row = idx >> 4, d4 = idx & 15;
            float4 v = *(const float4*)&Kb[(size_t)(kc*64 + row)*64 + d4*4];
            unsigned u01 = pack_h2(v.x, v.y), u23 = pack_h2(v.z, v.w);
            *(unsigned*)&Ks[row*QS + d4*4]     = u01;
            *(unsigned*)&Ks[row*QS + d4*4 + 2] = u23;
        }
        // stage V chunk transposed: Vt[d][key]
#pragma unroll
        for (int i = 0; i < 16; i++) {
            int idx = tid + i*256;
            int key = idx >> 6, d = idx & 63;
            Vt[d*QS + key] = __float2half(Vb[(size_t)(kc*64 + key)*64 + d]);
        }
        __syncthreads();

        // S = Q . K^T
        float sc[2][8][4];
#pragma unroll
        for (int mt = 0; mt < 2; mt++)
#pragma unroll
            for (int nt = 0; nt < 8; nt++)
#pragma unroll
                for (int i = 0; i < 4; i++) sc[mt][nt][i] = 0.f;
#pragma unroll
        for (int kt = 0; kt < 4; kt++) {
#pragma unroll
            for (int nt = 0; nt < 8; nt++) {
                unsigned b0, b1;
                ldsm2(b0, b1, bK + (unsigned)(nt*8*QS*2) + kt*32);
                mma_op(sc[0][nt], aQ[0][kt][0], aQ[0][kt][1], aQ[0][kt][2], aQ[0][kt][3], b0, b1);
                mma_op(sc[1][nt], aQ[1][kt][0], aQ[1][kt][1], aQ[1][kt][2], aQ[1][kt][3], b0, b1);
            }
        }

        // exp + rowsum
#pragma unroll
        for (int mt = 0; mt < 2; mt++)
#pragma unroll
            for (int nt = 0; nt < 8; nt++) {
                float p0 = __expf(sc[mt][nt][0] * 0.125f);
                float p1 = __expf(sc[mt][nt][1] * 0.125f);
                float p2 = __expf(sc[mt][nt][2] * 0.125f);
                float p3 = __expf(sc[mt][nt][3] * 0.125f);
                rs[mt][0] += p0 + p1;
                rs[mt][1] += p2 + p3;
                sc[mt][nt][0] = p0; sc[mt][nt][1] = p1;
                sc[mt][nt][2] = p2; sc[mt][nt][3] = p3;
            }

        // ctx += P . V
#pragma unroll
        for (int kt2 = 0; kt2 < 4; kt2++) {
            unsigned aP[2][4];
#pragma unroll
            for (int mt = 0; mt < 2; mt++) {
                aP[mt][0] = pack_h2(sc[mt][2*kt2][0],   sc[mt][2*kt2][1]);
                aP[mt][1] = pack_h2(sc[mt][2*kt2][2],   sc[mt][2*kt2][3]);
                aP[mt][2] = pack_h2(sc[mt][2*kt2+1][0], sc[mt][2*kt2+1][1]);
                aP[mt][3] = pack_h2(sc[mt][2*kt2+1][2], sc[mt][2*kt2+1][3]);
            }
#pragma unroll
            for (int nt = 0; nt < 8; nt++) {
                unsigned b0, b1;
                ldsm2(b0, b1, bV + (unsigned)(nt*8*QS*2) + kt2*32);
                mma_op(oacc[0][nt], aP[0][0], aP[0][1], aP[0][2], aP[0][3], b0, b1);
                mma_op(oacc[1][nt], aP[1][0], aP[1][1], aP[1][2], aP[1][3], b0, b1);
            }
        }
        __syncthreads();
    }

#pragma unroll
    for (int mt = 0; mt < 2; mt++)
#pragma unroll
        for (int j = 0; j < 2; j++) {
            rs[mt][j] += __shfl_xor_sync(0xffffffffu, rs[mt][j], 1);
            rs[mt][j] += __shfl_xor_sync(0xffffffffu, rs[mt][j], 2);
        }

    const int r = lane >> 2, c = lane & 3;
#pragma unroll
    for (int mt = 0; mt < 2; mt++) {
        float inv0 = 1.f / rs[mt][0];
        float inv1 = 1.f / rs[mt][1];
        int row0 = w*32 + mt*16 + r;
        int row1 = row0 + 8;
#pragma unroll
        for (int nt = 0; nt < 8; nt++) {
            int col = h*64 + nt*8 + 2*c;
            *(unsigned*)&CTXh[((size_t)(b*TT + row0))*HH + col] =
                pack_h2(oacc[mt][nt][0]*inv0, oacc[mt][nt][1]*inv0);
            *(unsigned*)&CTXh[((size_t)(b*TT + row1))*HH + col] =
                pack_h2(oacc[mt][nt][2]*inv1, oacc[mt][nt][3]*inv1);
        }
    }
}

// ---------------- final HMMA: out = W2 . relu([Lgh|CTXh] @ WfinH^T + b1f) + b2 ----------------
__global__ void __launch_bounds__(256) final_hmma(const float* __restrict__ W2,
                                                  const float* __restrict__ b2p,
                                                  float* __restrict__ out) {
    extern __shared__ char sm[];
    __half* Xs   = (__half*)sm;                       // 32*136
    __half* Wsm  = (__half*)(sm + 32*FS*2);           // 256*136
    float*  redm = (float*)(sm + 32*FS*2 + 256*FS*2); // 4*32
    const int m0 = blockIdx.x * 32;
    const int tid = threadIdx.x, w = tid >> 5, lane = tid & 31;
    const int mt = w >> 2, nq = w & 3;

    float acc[8][4];
#pragma unroll
    for (int i = 0; i < 8; i++)
#pragma unroll
        for (int j = 0; j < 4; j++) acc[i][j] = 0.f;

    const int arow = (lane & 7) + (((lane >> 3) & 1) << 3);
    const int akoff = ((lane >> 4) & 1) * 8;
    const unsigned abase = (unsigned)__cvta_generic_to_shared(Xs)
                         + (unsigned)(((mt*16 + arow)*FS + akoff)*2);
    const unsigned bbase = (unsigned)__cvta_generic_to_shared(Wsm)
                         + (unsigned)((((nq*64 + (lane & 7))*FS) + ((lane >> 3) & 1)*8)*2);

    for (int ch = 0; ch < 4; ch++) {
        const __half* xsrc = (ch < 2) ? Lgh : CTXh;
        int kc = (ch & 1) * 128;
#pragma unroll
        for (int i = 0; i < 2; i++) {
            int idx = tid + i*256;
            int row = idx >> 4, q = idx & 15;
            *(uint4*)(Xs + row*FS + q*8) =
                *(const uint4*)(xsrc + (size_t)(m0+row)*256 + kc + q*8);
        }
#pragma unroll
        for (int i = 0; i < 16; i++) {
            int idx = tid + i*256;
            int row = idx >> 4, q = idx & 15;
            *(uint4*)(Wsm + row*FS + q*8) =
                *(const uint4*)(WfinH + (size_t)row*512 + ch*128 + q*8);
        }
        __syncthreads();
#pragma unroll
        for (int kt = 0; kt < 8; kt++) {
            unsigned a0,a1,a2,a3;
            ldsm4(a0,a1,a2,a3, abase + kt*32);
#pragma unroll
            for (int nt = 0; nt < 8; nt++) {
                unsigned b0,b1;
                ldsm2(b0,b1, bbase + (unsigned)(nt*8*FS*2) + kt*32);
                mma_op(acc[nt], a0,a1,a2,a3, b0,b1);
            }
        }
        __syncthreads();
    }

    const int r = lane >> 2, c = lane & 3;
    float s0 = 0.f, s1 = 0.f;
#pragma unroll
    for (int nt = 0; nt < 8; nt++) {
        int nn = nq*64 + nt*8 + 2*c;
        float bb0 = b1fw[nn], bb1v = b1fw[nn+1];
        float w20 = W2[nn],   w21 = W2[nn+1];
        s0 += w20*fmaxf(acc[nt][0] + bb0, 0.f) + w21*fmaxf(acc[nt][1] + bb1v, 0.f);
        s1 += w20*fmaxf(acc[nt][2] + bb0, 0.f) + w21*fmaxf(acc[nt][3] + bb1v, 0.f);
    }
    s0 += __shfl_xor_sync(0xffffffffu, s0, 1);
    s0 += __shfl_xor_sync(0xffffffffu, s0, 2);
    s1 += __shfl_xor_sync(0xffffffffu, s1, 1);
    s1 += __shfl_xor_sync(0xffffffffu, s1, 2);
    if ((lane & 3) == 0) {
        redm[nq*32 + mt*16 + r]     = s0;
        redm[nq*32 + mt*16 + 8 + r] = s1;
    }
    __syncthreads();
    if (tid < 32)
        out[m0 + tid] = b2p[0] + redm[tid] + redm[32 + tid] + redm[64 + tid] + redm[96 + tid];
}

// ---------------- launch ----------------
extern "C" void kernel_launch(void* const* d_in, const int* in_sizes, int n_in,
                              void* d_out, int out_size) {
    (void)in_sizes; (void)n_in; (void)out_size;
    const float* F     = (const float*)d_in[0];
    const float* Wih0  = (const float*)d_in[1];
    const float* Whh0  = (const float*)d_in[2];
    const float* bih0  = (const float*)d_in[3];
    const float* bhh0  = (const float*)d_in[4];
    const float* Wih1  = (const float*)d_in[5];
    const float* Whh1  = (const float*)d_in[6];
    const float* bih1  = (const float*)d_in[7];
    const float* bhh1  = (const float*)d_in[8];
    const float* Winp  = (const float*)d_in[9];
    const float* binp  = (const float*)d_in[10];
    const float* Wop   = (const float*)d_in[11];
    const float* bop   = (const float*)d_in[12];
    const float* W1    = (const float*)d_in[13];
    const float* b1    = (const float*)d_in[14];
    const float* W2    = (const float*)d_in[15];
    const float* b2    = (const float*)d_in[16];
    float* out = (float*)d_out;

    const int SCAN_SMEM = 60416;
    const int QKV_SMEM  = (128*XS + 64*XS)*2;            // 101376
    const int ATT_SMEM  = 256*QS*2 + 64*QS*2 + 64*QS*2;  // 55296
    const int FIN_SMEM  = (32*FS + 256*FS)*2 + 4*32*4;   // 78848
    cudaFuncSetAttribute(scan_kernel, cudaFuncAttributeMaxDynamicSharedMemorySize, SCAN_SMEM);
    cudaFuncSetAttribute(qkv_hmma,    cudaFuncAttributeMaxDynamicSharedMemorySize, QKV_SMEM);
    cudaFuncSetAttribute(attn_hmma,   cudaFuncAttributeMaxDynamicSharedMemorySize, ATT_SMEM);
    cudaFuncSetAttribute(final_hmma,  cudaFuncAttributeMaxDynamicSharedMemorySize, FIN_SMEM);

    prep_frag<<<4544, 256>>>(Wih0, Whh0, Wih1, Whh1, W1, Winp);
    prep_wcomb<<<256, 256>>>(W1, Wop);
    prep_b1f<<<1, 256>>>(b1, bop, W1);
    scan_kernel<<<128, 512, SCAN_SMEM>>>(F, bih0, bhh0, bih1, bhh1, b1, W2, b2);
    qkv_hmma<<<dim3(1024, 12), 256, QKV_SMEM>>>(binp);
    attn_hmma<<<dim3(512, 4), 256, ATT_SMEM>>>();
    final_hmma<<<4096, 256, FIN_SMEM>>>(W2, b2, out);
}